// round 5
// baseline (speedup 1.0000x reference)
#include <cuda_runtime.h>
#include <cstdint>

// ---------------- problem dims ----------------
#define B_    64
#define T_    100
#define INF_  700
#define RED_  256
#define WID_  4096
#define CLS_  20
#define ROWS_ (B_*T_)          // 6400
#define KC_   1280             // conv im2col K (256*5)
#define NELEM_ (ROWS_*WID_)    // 26214400

// ---------------- scratch (static device globals; no alloc allowed) ----------------
__device__ unsigned g_absmax[4];
__device__ float g_qsp[RED_*INF_];
__device__ float g_qfc1[WID_*RED_];
__device__ float g_qfc2[CLS_*WID_];
__device__ float g_convWt[RED_*KC_];
__device__ float g_xp[ROWS_*RED_];
__device__ float g_x5[(size_t)ROWS_*KC_];
__device__ float g_co[ROWS_*RED_];
__device__ float g_wsum[B_*WID_];

// ---------------- threefry2x32 (JAX-compatible, partitionable mode) ----------------
__host__ __device__ constexpr unsigned rotl32c(unsigned v, int s) {
    return (v << s) | (v >> (32 - s));
}
struct K2 { unsigned a, b; };
constexpr K2 tf_const(unsigned k0, unsigned k1, unsigned x0, unsigned x1) {
    unsigned ks2 = k0 ^ k1 ^ 0x1BD11BDAu;
    unsigned ks[3] = {k0, k1, ks2};
    x0 += k0; x1 += k1;
    const int R[20] = {13,15,26,6, 17,29,16,24, 13,15,26,6, 17,29,16,24, 13,15,26,6};
    for (int g = 0; g < 5; ++g) {
        for (int j = 0; j < 4; ++j) { x0 += x1; x1 = rotl32c(x1, R[g*4+j]); x1 ^= x0; }
        x0 += ks[(g+1)%3];
        x1 += ks[(g+2)%3] + (unsigned)(g+1);
    }
    return K2{x0, x1};
}
constexpr K2 SUBKEY = tf_const(0u, 42u, 0u, 1u);
constexpr unsigned SK0 = SUBKEY.a;
constexpr unsigned SK1 = SUBKEY.b;

__device__ __forceinline__ uint2 tf2x32(unsigned k0, unsigned k1, unsigned x0, unsigned x1) {
    unsigned ks2 = k0 ^ k1 ^ 0x1BD11BDAu;
    x0 += k0; x1 += k1;
#define TFR(r) { x0 += x1; x1 = __funnelshift_l(x1, x1, (r)); x1 ^= x0; }
    TFR(13) TFR(15) TFR(26) TFR(6)   x0 += k1;  x1 += ks2 + 1u;
    TFR(17) TFR(29) TFR(16) TFR(24)  x0 += ks2; x1 += k0  + 2u;
    TFR(13) TFR(15) TFR(26) TFR(6)   x0 += k0;  x1 += k1  + 3u;
    TFR(17) TFR(29) TFR(16) TFR(24)  x0 += k1;  x1 += ks2 + 4u;
    TFR(13) TFR(15) TFR(26) TFR(6)   x0 += ks2; x1 += k0  + 5u;
#undef TFR
    return make_uint2(x0, x1);
}
__device__ __forceinline__ unsigned rbits32(unsigned idx) {
    uint2 r = tf2x32(SK0, SK1, 0u, idx);
    return r.x ^ r.y;
}

// ---------------- small kernels ----------------
__global__ void init_k() {
    if (threadIdx.x < 4) g_absmax[threadIdx.x] = 0u;
}
__global__ void absmax_k(const float* __restrict__ W, int n, int which) {
    float m = 0.0f;
    for (int i = blockIdx.x*blockDim.x + threadIdx.x; i < n; i += gridDim.x*blockDim.x)
        m = fmaxf(m, fabsf(W[i]));
    #pragma unroll
    for (int o = 16; o; o >>= 1) m = fmaxf(m, __shfl_xor_sync(0xffffffffu, m, o));
    if ((threadIdx.x & 31) == 0) atomicMax(&g_absmax[which], __float_as_uint(m));
}
__global__ void quant_k(const float* __restrict__ W, float* __restrict__ Q, int n, int which) {
    float scale = fmaxf(__fdiv_rn(__uint_as_float(g_absmax[which]), 7.0f), 1e-8f);
    int i = blockIdx.x*blockDim.x + threadIdx.x;
    if (i < n) Q[i] = __fmul_rn(rintf(__fdiv_rn(W[i], scale)), scale);
}
__global__ void convT_k(const float* __restrict__ convW) {
    int idx = blockIdx.x*blockDim.x + threadIdx.x;
    if (idx >= RED_*KC_) return;
    int o = idx / KC_, rem = idx % KC_;
    int k = rem >> 8, i = rem & 255;
    g_convWt[idx] = convW[o*KC_ + i*5 + k];
}
__global__ void im2col_k() {
    int idx = blockIdx.x*blockDim.x + threadIdx.x;
    if (idx >= ROWS_*KC_) return;
    int r = idx / KC_, rem = idx % KC_;
    int k = rem >> 8, i = rem & 255;
    int t = r % T_, b = r / T_;
    int ts = t + k - 2;
    g_x5[idx] = (ts >= 0 && ts < T_) ? g_xp[(b*T_ + ts)*RED_ + i] : 0.0f;
}

// ---------------- double-buffered fp32 SGEMM 128x128x8 ----------------
// C[M,N] = epi(A[M,K] @ B[N,K]^T + bias); 256 thr, 8 warps (64x32 tiles), 8x8 microtile.
__device__ __forceinline__ void drive_spike(float pre, float lat, float gabs,
                                            unsigned row, unsigned col,
                                            float& d_out, float& s_out) {
    float spl = fmaxf(pre, 0.0f) + log1pf(expf(-fabsf(pre)));
    float d   = (spl * lat) * gabs;
    unsigned bits = rbits32(row * (unsigned)WID_ + col);
    float u = __uint_as_float((bits >> 9) | 0x3f800000u) - 1.0f;
    d_out = d;
    s_out = (d >= 10.0f) ? 1.0f : ((logf(u) > -d) ? 1.0f : 0.0f);
}

template<int EPI>
__global__ __launch_bounds__(256, 2)
void sgemm_k(const float* __restrict__ A, const float* __restrict__ B,
             const float* __restrict__ bias, float* __restrict__ C,
             int K, int N,
             const float* __restrict__ latent, const float* __restrict__ gainp,
             float* __restrict__ drv, float* __restrict__ spk)
{
    __shared__ float sA[2][8][128];
    __shared__ float sB[2][8][128];

    const int tid  = threadIdx.x;
    const int lane = tid & 31;
    const int wid  = tid >> 5;
    const int lr   = lane >> 2;          // 0..7
    const int lc   = lane & 3;           // 0..3
    const int wm   = (wid & 1) * 64;
    const int wn   = (wid >> 1) * 32;
    const int bm0  = blockIdx.y * 128, bn0 = blockIdx.x * 128;

    const int lrow = tid >> 1;           // 0..127 loader row
    const int lc4  = (tid & 1) * 4;      // 0 or 4

    const float* Abase = A + (size_t)(bm0 + lrow) * K + lc4;
    const float* Bbase = B + (size_t)(bn0 + lrow) * K + lc4;

    float acc[2][2][4][4];
    #pragma unroll
    for (int im = 0; im < 2; ++im)
        #pragma unroll
        for (int in = 0; in < 2; ++in)
            #pragma unroll
            for (int i = 0; i < 4; ++i)
                #pragma unroll
                for (int j = 0; j < 4; ++j) acc[im][in][i][j] = 0.0f;

    const int nch = (K + 7) >> 3;
    float4 va, vb;
    {   // prologue: chunk 0
        int c = lc4;
        va = (c < K) ? *reinterpret_cast<const float4*>(Abase) : make_float4(0,0,0,0);
        vb = (c < K) ? *reinterpret_cast<const float4*>(Bbase) : make_float4(0,0,0,0);
        sA[0][lc4+0][lrow] = va.x; sA[0][lc4+1][lrow] = va.y;
        sA[0][lc4+2][lrow] = va.z; sA[0][lc4+3][lrow] = va.w;
        sB[0][lc4+0][lrow] = vb.x; sB[0][lc4+1][lrow] = vb.y;
        sB[0][lc4+2][lrow] = vb.z; sB[0][lc4+3][lrow] = vb.w;
        __syncthreads();
    }

    int p = 0;
    for (int ch = 0; ch < nch; ++ch) {
        const bool more = (ch + 1 < nch);
        if (more) {
            int c = (ch + 1) * 8 + lc4;
            va = (c < K) ? *reinterpret_cast<const float4*>(Abase + (ch+1)*8) : make_float4(0,0,0,0);
            vb = (c < K) ? *reinterpret_cast<const float4*>(Bbase + (ch+1)*8) : make_float4(0,0,0,0);
        }
        #pragma unroll
        for (int kk = 0; kk < 8; ++kk) {
            float4 a0 = *reinterpret_cast<const float4*>(&sA[p][kk][wm + lr*4]);
            float4 a1 = *reinterpret_cast<const float4*>(&sA[p][kk][wm + 32 + lr*4]);
            float4 b0 = *reinterpret_cast<const float4*>(&sB[p][kk][wn + lc*4]);
            float4 b1 = *reinterpret_cast<const float4*>(&sB[p][kk][wn + 16 + lc*4]);
            const float* af[2] = { &a0.x, &a1.x };
            const float* bf[2] = { &b0.x, &b1.x };
            #pragma unroll
            for (int im = 0; im < 2; ++im)
                #pragma unroll
                for (int i = 0; i < 4; ++i) {
                    float av = af[im][i];
                    #pragma unroll
                    for (int in = 0; in < 2; ++in)
                        #pragma unroll
                        for (int j = 0; j < 4; ++j)
                            acc[im][in][i][j] = fmaf(av, bf[in][j], acc[im][in][i][j]);
                }
        }
        if (more) {
            int q = p ^ 1;
            sA[q][lc4+0][lrow] = va.x; sA[q][lc4+1][lrow] = va.y;
            sA[q][lc4+2][lrow] = va.z; sA[q][lc4+3][lrow] = va.w;
            sB[q][lc4+0][lrow] = vb.x; sB[q][lc4+1][lrow] = vb.y;
            sB[q][lc4+2][lrow] = vb.z; sB[q][lc4+3][lrow] = vb.w;
            __syncthreads();
            p = q;
        }
    }

    // ---- epilogue ----
    if (EPI == 0) {
        #pragma unroll
        for (int im = 0; im < 2; ++im)
            #pragma unroll
            for (int i = 0; i < 4; ++i) {
                int row = bm0 + wm + im*32 + lr*4 + i;
                #pragma unroll
                for (int in = 0; in < 2; ++in) {
                    int col = bn0 + wn + in*16 + lc*4;
                    float4 v;
                    v.x = fmaxf(acc[im][in][i][0] + __ldg(bias + col + 0), 0.0f);
                    v.y = fmaxf(acc[im][in][i][1] + __ldg(bias + col + 1), 0.0f);
                    v.z = fmaxf(acc[im][in][i][2] + __ldg(bias + col + 2), 0.0f);
                    v.w = fmaxf(acc[im][in][i][3] + __ldg(bias + col + 3), 0.0f);
                    *reinterpret_cast<float4*>(C + (size_t)row*N + col) = v;
                }
            }
    } else {
        const float gabs = fabsf(gainp[0]);
        #pragma unroll
        for (int im = 0; im < 2; ++im)
            #pragma unroll
            for (int i = 0; i < 4; ++i) {
                int row = bm0 + wm + im*32 + lr*4 + i;
                float lat = __ldg(latent + (row % T_));
                #pragma unroll
                for (int in = 0; in < 2; ++in) {
                    int col = bn0 + wn + in*16 + lc*4;
                    float4 dv, sv;
                    float pre0 = acc[im][in][i][0] + __ldg(bias + col + 0);
                    float pre1 = acc[im][in][i][1] + __ldg(bias + col + 1);
                    float pre2 = acc[im][in][i][2] + __ldg(bias + col + 2);
                    float pre3 = acc[im][in][i][3] + __ldg(bias + col + 3);
                    drive_spike(pre0, lat, gabs, (unsigned)row, (unsigned)(col+0), dv.x, sv.x);
                    drive_spike(pre1, lat, gabs, (unsigned)row, (unsigned)(col+1), dv.y, sv.y);
                    drive_spike(pre2, lat, gabs, (unsigned)row, (unsigned)(col+2), dv.z, sv.z);
                    drive_spike(pre3, lat, gabs, (unsigned)row, (unsigned)(col+3), dv.w, sv.w);
                    size_t ob = (size_t)row * WID_ + col;
                    *reinterpret_cast<float4*>(drv + ob) = dv;
                    *reinterpret_cast<float4*>(spk + ob) = sv;
                }
            }
    }
}

// ---------------- decay-weighted temporal reduction ----------------
__global__ void weighted_k(const float* __restrict__ spikes) {
    __shared__ float decay[T_];
    int tid = threadIdx.x;
    if (tid < T_) decay[tid] = expf(-2.0f + (float)tid * (2.0f/99.0f));
    __syncthreads();
    int idx = blockIdx.x * blockDim.x + tid;
    if (idx >= B_*WID_) return;
    int b = idx >> 12, w = idx & (WID_-1);
    const float* sp = spikes + (size_t)b*T_*WID_ + w;
    float s = 0.0f;
    #pragma unroll 4
    for (int t = 0; t < T_; ++t) s += sp[(size_t)t*WID_] * decay[t];
    g_wsum[idx] = s;
}

// ---------------- logits ----------------
__global__ void logits_k(const float* __restrict__ bias, float* __restrict__ out) {
    int bc = blockIdx.x;
    int b = bc / CLS_, c = bc % CLS_;
    const float* wr = g_wsum + (size_t)b*WID_;
    const float* fr = g_qfc2 + (size_t)c*WID_;
    float s = 0.0f;
    for (int i = threadIdx.x; i < WID_; i += 128) s += wr[i]*fr[i];
    #pragma unroll
    for (int o = 16; o; o >>= 1) s += __shfl_xor_sync(0xffffffffu, s, o);
    __shared__ float red[4];
    if ((threadIdx.x & 31) == 0) red[threadIdx.x >> 5] = s;
    __syncthreads();
    if (threadIdx.x == 0) out[bc] = (red[0]+red[1]+red[2]+red[3]) + bias[c];
}

// ---------------- launcher ----------------
extern "C" void kernel_launch(void* const* d_in, const int* in_sizes, int n_in,
                              void* d_out, int out_size) {
    (void)in_sizes; (void)n_in; (void)out_size;
    const float* x        = (const float*)d_in[0];
    const float* latent   = (const float*)d_in[1];
    const float* spatialW = (const float*)d_in[2];
    const float* spatialB = (const float*)d_in[3];
    const float* convW    = (const float*)d_in[4];
    const float* convB    = (const float*)d_in[5];
    const float* fc1W     = (const float*)d_in[6];
    const float* fc1B     = (const float*)d_in[7];
    const float* fc2W     = (const float*)d_in[8];
    const float* fc2B     = (const float*)d_in[9];
    const float* gain     = (const float*)d_in[10];

    float* out        = (float*)d_out;
    float* out_logits = out;
    float* out_spk    = out + (CLS_*B_);
    float* out_drv    = out + (CLS_*B_) + (size_t)NELEM_;

    float *qsp, *qfc1, *qfc2, *cwt, *xp, *x5, *co;
    cudaGetSymbolAddress((void**)&qsp,  g_qsp);
    cudaGetSymbolAddress((void**)&qfc1, g_qfc1);
    cudaGetSymbolAddress((void**)&qfc2, g_qfc2);
    cudaGetSymbolAddress((void**)&cwt,  g_convWt);
    cudaGetSymbolAddress((void**)&xp,   g_xp);
    cudaGetSymbolAddress((void**)&x5,   g_x5);
    cudaGetSymbolAddress((void**)&co,   g_co);

    init_k<<<1, 32>>>();
    absmax_k<<<128, 256>>>(spatialW, RED_*INF_,  0);
    absmax_k<<<256, 256>>>(fc1W,     WID_*RED_,  1);
    absmax_k<<<128, 256>>>(fc2W,     CLS_*WID_,  2);
    quant_k<<<(RED_*INF_ + 255)/256, 256>>>(spatialW, qsp,  RED_*INF_, 0);
    quant_k<<<(WID_*RED_ + 255)/256, 256>>>(fc1W,     qfc1, WID_*RED_, 1);
    quant_k<<<(CLS_*WID_ + 255)/256, 256>>>(fc2W,     qfc2, CLS_*WID_, 2);
    convT_k<<<(RED_*KC_ + 255)/256, 256>>>(convW);

    // GEMM1: xp = relu(x @ qsp^T + b)   M=6400 N=256 K=700
    sgemm_k<0><<<dim3(RED_/128, ROWS_/128), 256>>>(
        x, qsp, spatialB, xp, INF_, RED_, nullptr, nullptr, nullptr, nullptr);
    im2col_k<<<(ROWS_*KC_ + 255)/256, 256>>>();
    // conv as GEMM: co = relu(x5 @ cwt^T + cb)   M=6400 N=256 K=1280
    sgemm_k<0><<<dim3(RED_/128, ROWS_/128), 256>>>(
        x5, cwt, convB, co, KC_, RED_, nullptr, nullptr, nullptr, nullptr);
    // GEMM2: drive/spike fused   M=6400 N=4096 K=256
    sgemm_k<1><<<dim3(WID_/128, ROWS_/128), 256>>>(
        co, qfc1, fc1B, nullptr, RED_, WID_, latent, gain, out_drv, out_spk);
    weighted_k<<<(B_*WID_ + 255)/256, 256>>>(out_spk);
    logits_k<<<B_*CLS_, 128>>>(fc2B, out_logits);
}

// round 6
// speedup vs baseline: 1.1235x; 1.1235x over previous
#include <cuda_runtime.h>
#include <cstdint>

// ---------------- problem dims ----------------
#define B_    64
#define T_    100
#define INF_  700
#define RED_  256
#define WID_  4096
#define CLS_  20
#define ROWS_ (B_*T_)          // 6400
#define KC_   1280             // conv im2col K (256*5)
#define NELEM_ (ROWS_*WID_)    // 26214400

// ---------------- scratch (static device globals; no alloc allowed) ----------------
__device__ unsigned g_absmax[4];
__device__ float g_qsp[RED_*INF_];
__device__ float g_qfc1[WID_*RED_];
__device__ float g_qfc2[CLS_*WID_];
__device__ float g_convWt[RED_*KC_];
__device__ float g_xp[ROWS_*RED_];
__device__ float g_x5[(size_t)ROWS_*KC_];
__device__ float g_co[ROWS_*RED_];
__device__ float g_wsum[B_*WID_];

// ---------------- threefry2x32 (JAX-compatible, partitionable mode) ----------------
__host__ __device__ constexpr unsigned rotl32c(unsigned v, int s) {
    return (v << s) | (v >> (32 - s));
}
struct K2 { unsigned a, b; };
constexpr K2 tf_const(unsigned k0, unsigned k1, unsigned x0, unsigned x1) {
    unsigned ks2 = k0 ^ k1 ^ 0x1BD11BDAu;
    unsigned ks[3] = {k0, k1, ks2};
    x0 += k0; x1 += k1;
    const int R[20] = {13,15,26,6, 17,29,16,24, 13,15,26,6, 17,29,16,24, 13,15,26,6};
    for (int g = 0; g < 5; ++g) {
        for (int j = 0; j < 4; ++j) { x0 += x1; x1 = rotl32c(x1, R[g*4+j]); x1 ^= x0; }
        x0 += ks[(g+1)%3];
        x1 += ks[(g+2)%3] + (unsigned)(g+1);
    }
    return K2{x0, x1};
}
constexpr K2 SUBKEY = tf_const(0u, 42u, 0u, 1u);
constexpr unsigned SK0 = SUBKEY.a;
constexpr unsigned SK1 = SUBKEY.b;

__device__ __forceinline__ uint2 tf2x32(unsigned k0, unsigned k1, unsigned x0, unsigned x1) {
    unsigned ks2 = k0 ^ k1 ^ 0x1BD11BDAu;
    x0 += k0; x1 += k1;
#define TFR(r) { x0 += x1; x1 = __funnelshift_l(x1, x1, (r)); x1 ^= x0; }
    TFR(13) TFR(15) TFR(26) TFR(6)   x0 += k1;  x1 += ks2 + 1u;
    TFR(17) TFR(29) TFR(16) TFR(24)  x0 += ks2; x1 += k0  + 2u;
    TFR(13) TFR(15) TFR(26) TFR(6)   x0 += k0;  x1 += k1  + 3u;
    TFR(17) TFR(29) TFR(16) TFR(24)  x0 += k1;  x1 += ks2 + 4u;
    TFR(13) TFR(15) TFR(26) TFR(6)   x0 += ks2; x1 += k0  + 5u;
#undef TFR
    return make_uint2(x0, x1);
}
__device__ __forceinline__ unsigned rbits32(unsigned idx) {
    uint2 r = tf2x32(SK0, SK1, 0u, idx);
    return r.x ^ r.y;
}

// ---------------- packed f32x2 helpers ----------------
__device__ __forceinline__ void ffma2(unsigned long long& acc,
                                      unsigned long long a,
                                      unsigned long long b) {
    asm("fma.rn.f32x2 %0, %1, %2, %0;" : "+l"(acc) : "l"(a), "l"(b));
}
__device__ __forceinline__ unsigned long long dup_f32x2(float x) {
    unsigned long long d;
    asm("mov.b64 %0, {%1, %1};" : "=l"(d) : "f"(x));
    return d;
}
__device__ __forceinline__ float2 unpack_f32x2(unsigned long long v) {
    float lo, hi;
    asm("mov.b64 {%0, %1}, %2;" : "=f"(lo), "=f"(hi) : "l"(v));
    return make_float2(lo, hi);
}

// ---------------- small kernels ----------------
__global__ void init_k() {
    if (threadIdx.x < 4) g_absmax[threadIdx.x] = 0u;
}
__global__ void absmax_k(const float* __restrict__ W, int n, int which) {
    float m = 0.0f;
    for (int i = blockIdx.x*blockDim.x + threadIdx.x; i < n; i += gridDim.x*blockDim.x)
        m = fmaxf(m, fabsf(W[i]));
    #pragma unroll
    for (int o = 16; o; o >>= 1) m = fmaxf(m, __shfl_xor_sync(0xffffffffu, m, o));
    if ((threadIdx.x & 31) == 0) atomicMax(&g_absmax[which], __float_as_uint(m));
}
__global__ void quant_k(const float* __restrict__ W, float* __restrict__ Q, int n, int which) {
    float scale = fmaxf(__fdiv_rn(__uint_as_float(g_absmax[which]), 7.0f), 1e-8f);
    int i = blockIdx.x*blockDim.x + threadIdx.x;
    if (i < n) Q[i] = __fmul_rn(rintf(__fdiv_rn(W[i], scale)), scale);
}
__global__ void convT_k(const float* __restrict__ convW) {
    int idx = blockIdx.x*blockDim.x + threadIdx.x;
    if (idx >= RED_*KC_) return;
    int o = idx / KC_, rem = idx % KC_;
    int k = rem >> 8, i = rem & 255;
    g_convWt[idx] = convW[o*KC_ + i*5 + k];
}
__global__ void im2col_k() {
    int idx = blockIdx.x*blockDim.x + threadIdx.x;
    if (idx >= ROWS_*KC_) return;
    int r = idx / KC_, rem = idx % KC_;
    int k = rem >> 8, i = rem & 255;
    int t = r % T_, b = r / T_;
    int ts = t + k - 2;
    g_x5[idx] = (ts >= 0 && ts < T_) ? g_xp[(b*T_ + ts)*RED_ + i] : 0.0f;
}

// ---------------- drive/spike epilogue ----------------
__device__ __forceinline__ void drive_spike(float pre, float lat, float gabs,
                                            unsigned row, unsigned col,
                                            float& d_out, float& s_out) {
    float spl = fmaxf(pre, 0.0f) + log1pf(expf(-fabsf(pre)));
    float d   = (spl * lat) * gabs;
    unsigned bits = rbits32(row * (unsigned)WID_ + col);
    float u = __uint_as_float((bits >> 9) | 0x3f800000u) - 1.0f;
    d_out = d;
    s_out = (d >= 10.0f) ? 1.0f : ((logf(u) > -d) ? 1.0f : 0.0f);
}

// ---------------- FFMA2 double-buffered SGEMM 128x128x16 ----------------
// C[M,N] = epi(A[M,K] @ B[N,K]^T + bias); 256 thr, 8 warps (64x32 tiles), 8x8 microtile.
// Inner product uses packed fma.rn.f32x2: exact fp32 products, column-paired accumulators.
template<int EPI>
__global__ __launch_bounds__(256, 2)
void sgemm_k(const float* __restrict__ A, const float* __restrict__ B,
             const float* __restrict__ bias, float* __restrict__ C,
             int K, int N,
             const float* __restrict__ latent, const float* __restrict__ gainp,
             float* __restrict__ drv, float* __restrict__ spk)
{
    __shared__ float sA[2][16][128];
    __shared__ float sB[2][16][128];

    const int tid  = threadIdx.x;
    const int lane = tid & 31;
    const int wid  = tid >> 5;
    const int lr   = lane >> 2;          // 0..7
    const int lc   = lane & 3;           // 0..3
    const int wm   = (wid & 1) * 64;
    const int wn   = (wid >> 1) * 32;
    const int bm0  = blockIdx.y * 128, bn0 = blockIdx.x * 128;

    // acc2[im][in][i][jp]: packed pair = output cols (jp*2, jp*2+1)
    unsigned long long acc2[2][2][4][2];
    #pragma unroll
    for (int im = 0; im < 2; ++im)
        #pragma unroll
        for (int in = 0; in < 2; ++in)
            #pragma unroll
            for (int i = 0; i < 4; ++i) {
                acc2[im][in][i][0] = 0ull;
                acc2[im][in][i][1] = 0ull;
            }

    const int nch = (K + 15) >> 4;
    float4 va[2], vb[2];

    // loader mapping: q = tid + 256*i -> row = q>>2 (0..127), c4 = (q&3)*4 (0..12)
    {   // prologue chunk 0
        #pragma unroll
        for (int i = 0; i < 2; ++i) {
            int q = tid + 256*i;
            int row = q >> 2, c = (q & 3) * 4;
            va[i] = (c < K) ? *reinterpret_cast<const float4*>(A + (size_t)(bm0+row)*K + c)
                            : make_float4(0,0,0,0);
            vb[i] = (c < K) ? *reinterpret_cast<const float4*>(B + (size_t)(bn0+row)*K + c)
                            : make_float4(0,0,0,0);
        }
        #pragma unroll
        for (int i = 0; i < 2; ++i) {
            int q = tid + 256*i;
            int row = q >> 2, c4 = (q & 3) * 4;
            sA[0][c4+0][row] = va[i].x; sA[0][c4+1][row] = va[i].y;
            sA[0][c4+2][row] = va[i].z; sA[0][c4+3][row] = va[i].w;
            sB[0][c4+0][row] = vb[i].x; sB[0][c4+1][row] = vb[i].y;
            sB[0][c4+2][row] = vb[i].z; sB[0][c4+3][row] = vb[i].w;
        }
        __syncthreads();
    }

    int p = 0;
    for (int ch = 0; ch < nch; ++ch) {
        const bool more = (ch + 1 < nch);
        if (more) {
            int k0 = (ch + 1) * 16;
            #pragma unroll
            for (int i = 0; i < 2; ++i) {
                int q = tid + 256*i;
                int row = q >> 2, c = k0 + (q & 3) * 4;
                va[i] = (c < K) ? *reinterpret_cast<const float4*>(A + (size_t)(bm0+row)*K + c)
                                : make_float4(0,0,0,0);
                vb[i] = (c < K) ? *reinterpret_cast<const float4*>(B + (size_t)(bn0+row)*K + c)
                                : make_float4(0,0,0,0);
            }
        }
        #pragma unroll
        for (int kk = 0; kk < 16; ++kk) {
            float4 a0 = *reinterpret_cast<const float4*>(&sA[p][kk][wm + lr*4]);
            float4 a1 = *reinterpret_cast<const float4*>(&sA[p][kk][wm + 32 + lr*4]);
            ulonglong2 b0 = *reinterpret_cast<const ulonglong2*>(&sB[p][kk][wn + lc*4]);
            ulonglong2 b1 = *reinterpret_cast<const ulonglong2*>(&sB[p][kk][wn + 16 + lc*4]);
            unsigned long long bp[2][2] = { { b0.x, b0.y }, { b1.x, b1.y } };
            const float av[2][4] = { { a0.x, a0.y, a0.z, a0.w },
                                     { a1.x, a1.y, a1.z, a1.w } };
            #pragma unroll
            for (int im = 0; im < 2; ++im)
                #pragma unroll
                for (int i = 0; i < 4; ++i) {
                    unsigned long long ad = dup_f32x2(av[im][i]);
                    #pragma unroll
                    for (int in = 0; in < 2; ++in) {
                        ffma2(acc2[im][in][i][0], ad, bp[in][0]);
                        ffma2(acc2[im][in][i][1], ad, bp[in][1]);
                    }
                }
        }
        if (more) {
            int q2 = p ^ 1;
            #pragma unroll
            for (int i = 0; i < 2; ++i) {
                int q = tid + 256*i;
                int row = q >> 2, c4 = (q & 3) * 4;
                sA[q2][c4+0][row] = va[i].x; sA[q2][c4+1][row] = va[i].y;
                sA[q2][c4+2][row] = va[i].z; sA[q2][c4+3][row] = va[i].w;
                sB[q2][c4+0][row] = vb[i].x; sB[q2][c4+1][row] = vb[i].y;
                sB[q2][c4+2][row] = vb[i].z; sB[q2][c4+3][row] = vb[i].w;
            }
            __syncthreads();
            p = q2;
        }
    }

    // ---- epilogue ----
    if (EPI == 0) {
        #pragma unroll
        for (int im = 0; im < 2; ++im)
            #pragma unroll
            for (int i = 0; i < 4; ++i) {
                int row = bm0 + wm + im*32 + lr*4 + i;
                #pragma unroll
                for (int in = 0; in < 2; ++in) {
                    int col = bn0 + wn + in*16 + lc*4;
                    float2 p01 = unpack_f32x2(acc2[im][in][i][0]);
                    float2 p23 = unpack_f32x2(acc2[im][in][i][1]);
                    float4 v;
                    v.x = fmaxf(p01.x + __ldg(bias + col + 0), 0.0f);
                    v.y = fmaxf(p01.y + __ldg(bias + col + 1), 0.0f);
                    v.z = fmaxf(p23.x + __ldg(bias + col + 2), 0.0f);
                    v.w = fmaxf(p23.y + __ldg(bias + col + 3), 0.0f);
                    *reinterpret_cast<float4*>(C + (size_t)row*N + col) = v;
                }
            }
    } else {
        const float gabs = fabsf(gainp[0]);
        #pragma unroll
        for (int im = 0; im < 2; ++im)
            #pragma unroll
            for (int i = 0; i < 4; ++i) {
                int row = bm0 + wm + im*32 + lr*4 + i;
                float lat = __ldg(latent + (row % T_));
                #pragma unroll
                for (int in = 0; in < 2; ++in) {
                    int col = bn0 + wn + in*16 + lc*4;
                    float2 p01 = unpack_f32x2(acc2[im][in][i][0]);
                    float2 p23 = unpack_f32x2(acc2[im][in][i][1]);
                    float4 dv, sv;
                    float pre0 = p01.x + __ldg(bias + col + 0);
                    float pre1 = p01.y + __ldg(bias + col + 1);
                    float pre2 = p23.x + __ldg(bias + col + 2);
                    float pre3 = p23.y + __ldg(bias + col + 3);
                    drive_spike(pre0, lat, gabs, (unsigned)row, (unsigned)(col+0), dv.x, sv.x);
                    drive_spike(pre1, lat, gabs, (unsigned)row, (unsigned)(col+1), dv.y, sv.y);
                    drive_spike(pre2, lat, gabs, (unsigned)row, (unsigned)(col+2), dv.z, sv.z);
                    drive_spike(pre3, lat, gabs, (unsigned)row, (unsigned)(col+3), dv.w, sv.w);
                    size_t ob = (size_t)row * WID_ + col;
                    *reinterpret_cast<float4*>(drv + ob) = dv;
                    *reinterpret_cast<float4*>(spk + ob) = sv;
                }
            }
    }
}

// ---------------- decay-weighted temporal reduction ----------------
__global__ void weighted_k(const float* __restrict__ spikes) {
    __shared__ float decay[T_];
    int tid = threadIdx.x;
    if (tid < T_) decay[tid] = expf(-2.0f + (float)tid * (2.0f/99.0f));
    __syncthreads();
    int idx = blockIdx.x * blockDim.x + tid;
    if (idx >= B_*WID_) return;
    int b = idx >> 12, w = idx & (WID_-1);
    const float* sp = spikes + (size_t)b*T_*WID_ + w;
    float s = 0.0f;
    #pragma unroll 4
    for (int t = 0; t < T_; ++t) s += sp[(size_t)t*WID_] * decay[t];
    g_wsum[idx] = s;
}

// ---------------- logits ----------------
__global__ void logits_k(const float* __restrict__ bias, float* __restrict__ out) {
    int bc = blockIdx.x;
    int b = bc / CLS_, c = bc % CLS_;
    const float* wr = g_wsum + (size_t)b*WID_;
    const float* fr = g_qfc2 + (size_t)c*WID_;
    float s = 0.0f;
    for (int i = threadIdx.x; i < WID_; i += 128) s += wr[i]*fr[i];
    #pragma unroll
    for (int o = 16; o; o >>= 1) s += __shfl_xor_sync(0xffffffffu, s, o);
    __shared__ float red[4];
    if ((threadIdx.x & 31) == 0) red[threadIdx.x >> 5] = s;
    __syncthreads();
    if (threadIdx.x == 0) out[bc] = (red[0]+red[1]+red[2]+red[3]) + bias[c];
}

// ---------------- launcher ----------------
extern "C" void kernel_launch(void* const* d_in, const int* in_sizes, int n_in,
                              void* d_out, int out_size) {
    (void)in_sizes; (void)n_in; (void)out_size;
    const float* x        = (const float*)d_in[0];
    const float* latent   = (const float*)d_in[1];
    const float* spatialW = (const float*)d_in[2];
    const float* spatialB = (const float*)d_in[3];
    const float* convW    = (const float*)d_in[4];
    const float* convB    = (const float*)d_in[5];
    const float* fc1W     = (const float*)d_in[6];
    const float* fc1B     = (const float*)d_in[7];
    const float* fc2W     = (const float*)d_in[8];
    const float* fc2B     = (const float*)d_in[9];
    const float* gain     = (const float*)d_in[10];

    float* out        = (float*)d_out;
    float* out_logits = out;
    float* out_spk    = out + (CLS_*B_);
    float* out_drv    = out + (CLS_*B_) + (size_t)NELEM_;

    float *qsp, *qfc1, *qfc2, *cwt, *xp, *x5, *co;
    cudaGetSymbolAddress((void**)&qsp,  g_qsp);
    cudaGetSymbolAddress((void**)&qfc1, g_qfc1);
    cudaGetSymbolAddress((void**)&qfc2, g_qfc2);
    cudaGetSymbolAddress((void**)&cwt,  g_convWt);
    cudaGetSymbolAddress((void**)&xp,   g_xp);
    cudaGetSymbolAddress((void**)&x5,   g_x5);
    cudaGetSymbolAddress((void**)&co,   g_co);

    init_k<<<1, 32>>>();
    absmax_k<<<128, 256>>>(spatialW, RED_*INF_,  0);
    absmax_k<<<256, 256>>>(fc1W,     WID_*RED_,  1);
    absmax_k<<<128, 256>>>(fc2W,     CLS_*WID_,  2);
    quant_k<<<(RED_*INF_ + 255)/256, 256>>>(spatialW, qsp,  RED_*INF_, 0);
    quant_k<<<(WID_*RED_ + 255)/256, 256>>>(fc1W,     qfc1, WID_*RED_, 1);
    quant_k<<<(CLS_*WID_ + 255)/256, 256>>>(fc2W,     qfc2, CLS_*WID_, 2);
    convT_k<<<(RED_*KC_ + 255)/256, 256>>>(convW);

    // GEMM1: xp = relu(x @ qsp^T + b)   M=6400 N=256 K=700
    sgemm_k<0><<<dim3(RED_/128, ROWS_/128), 256>>>(
        x, qsp, spatialB, xp, INF_, RED_, nullptr, nullptr, nullptr, nullptr);
    im2col_k<<<(ROWS_*KC_ + 255)/256, 256>>>();
    // conv as GEMM: co = relu(x5 @ cwt^T + cb)   M=6400 N=256 K=1280
    sgemm_k<0><<<dim3(RED_/128, ROWS_/128), 256>>>(
        x5, cwt, convB, co, KC_, RED_, nullptr, nullptr, nullptr, nullptr);
    // GEMM2: drive/spike fused   M=6400 N=4096 K=256
    sgemm_k<1><<<dim3(WID_/128, ROWS_/128), 256>>>(
        co, qfc1, fc1B, nullptr, RED_, WID_, latent, gain, out_drv, out_spk);
    weighted_k<<<(B_*WID_ + 255)/256, 256>>>(out_spk);
    logits_k<<<B_*CLS_, 128>>>(fc2B, out_logits);
}

// round 8
// speedup vs baseline: 1.2471x; 1.1100x over previous
#include <cuda_runtime.h>
#include <cstdint>

// ---------------- problem dims ----------------
#define B_    64
#define T_    100
#define INF_  700
#define RED_  256
#define WID_  4096
#define CLS_  20
#define ROWS_ (B_*T_)          // 6400
#define KC_   1280             // conv im2col K (256*5)
#define NELEM_ (ROWS_*WID_)    // 26214400
#define WCAP  (1u<<22)         // borderline worklist capacity
#define MARGIN 5e-4f

// ---------------- scratch (static device globals; no alloc allowed) ----------------
__device__ unsigned g_absmax[4];
__device__ unsigned g_count;
__device__ unsigned g_worklist[WCAP];
__device__ float g_qsp[RED_*INF_];
__device__ float g_qfc1[WID_*RED_];
__device__ float g_qfc2[CLS_*WID_];
__device__ float g_convWt[RED_*KC_];
__device__ float g_xp[ROWS_*RED_];
__device__ float g_co[ROWS_*RED_];
__device__ float g_wsum[B_*WID_];

// ---------------- threefry2x32 (JAX-compatible, partitionable mode) ----------------
__host__ __device__ constexpr unsigned rotl32c(unsigned v, int s) {
    return (v << s) | (v >> (32 - s));
}
struct K2 { unsigned a, b; };
constexpr K2 tf_const(unsigned k0, unsigned k1, unsigned x0, unsigned x1) {
    unsigned ks2 = k0 ^ k1 ^ 0x1BD11BDAu;
    unsigned ks[3] = {k0, k1, ks2};
    x0 += k0; x1 += k1;
    const int R[20] = {13,15,26,6, 17,29,16,24, 13,15,26,6, 17,29,16,24, 13,15,26,6};
    for (int g = 0; g < 5; ++g) {
        for (int j = 0; j < 4; ++j) { x0 += x1; x1 = rotl32c(x1, R[g*4+j]); x1 ^= x0; }
        x0 += ks[(g+1)%3];
        x1 += ks[(g+2)%3] + (unsigned)(g+1);
    }
    return K2{x0, x1};
}
constexpr K2 SUBKEY = tf_const(0u, 42u, 0u, 1u);
constexpr unsigned SK0 = SUBKEY.a;
constexpr unsigned SK1 = SUBKEY.b;

__device__ __forceinline__ uint2 tf2x32(unsigned k0, unsigned k1, unsigned x0, unsigned x1) {
    unsigned ks2 = k0 ^ k1 ^ 0x1BD11BDAu;
    x0 += k0; x1 += k1;
#define TFR(r) { x0 += x1; x1 = __funnelshift_l(x1, x1, (r)); x1 ^= x0; }
    TFR(13) TFR(15) TFR(26) TFR(6)   x0 += k1;  x1 += ks2 + 1u;
    TFR(17) TFR(29) TFR(16) TFR(24)  x0 += ks2; x1 += k0  + 2u;
    TFR(13) TFR(15) TFR(26) TFR(6)   x0 += k0;  x1 += k1  + 3u;
    TFR(17) TFR(29) TFR(16) TFR(24)  x0 += k1;  x1 += ks2 + 4u;
    TFR(13) TFR(15) TFR(26) TFR(6)   x0 += ks2; x1 += k0  + 5u;
#undef TFR
    return make_uint2(x0, x1);
}
__device__ __forceinline__ unsigned rbits32(unsigned idx) {
    uint2 r = tf2x32(SK0, SK1, 0u, idx);
    return r.x ^ r.y;
}

// ---------------- packed f32x2 helpers ----------------
__device__ __forceinline__ void ffma2(unsigned long long& acc,
                                      unsigned long long a,
                                      unsigned long long b) {
    asm("fma.rn.f32x2 %0, %1, %2, %0;" : "+l"(acc) : "l"(a), "l"(b));
}
__device__ __forceinline__ unsigned long long dup_f32x2(float x) {
    unsigned long long d;
    asm("mov.b64 %0, {%1, %1};" : "=l"(d) : "f"(x));
    return d;
}
__device__ __forceinline__ float2 unpack_f32x2(unsigned long long v) {
    float lo, hi;
    asm("mov.b64 {%0, %1}, %2;" : "=f"(lo), "=f"(hi) : "l"(v));
    return make_float2(lo, hi);
}

// ---------------- tf32 helpers ----------------
__device__ __forceinline__ float tf32_hi(float x) {
    uint32_t u; asm("cvt.rna.tf32.f32 %0, %1;" : "=r"(u) : "f"(x));
    return __uint_as_float(u);
}
#define MMA_TF32(c, a, b) \
    asm volatile("mma.sync.aligned.m16n8k8.row.col.f32.tf32.tf32.f32 " \
        "{%0,%1,%2,%3}, {%4,%5,%6,%7}, {%8,%9}, {%0,%1,%2,%3};" \
        : "+f"((c)[0]), "+f"((c)[1]), "+f"((c)[2]), "+f"((c)[3]) \
        : "r"(__float_as_uint((a)[0])), "r"(__float_as_uint((a)[1])), \
          "r"(__float_as_uint((a)[2])), "r"(__float_as_uint((a)[3])), \
          "r"(__float_as_uint((b)[0])), "r"(__float_as_uint((b)[1])))

// ---------------- small kernels ----------------
__global__ void init_k() {
    if (threadIdx.x < 4) g_absmax[threadIdx.x] = 0u;
    if (threadIdx.x == 0) g_count = 0u;
}
__global__ void absmax_k(const float* __restrict__ W, int n, int which) {
    float m = 0.0f;
    for (int i = blockIdx.x*blockDim.x + threadIdx.x; i < n; i += gridDim.x*blockDim.x)
        m = fmaxf(m, fabsf(W[i]));
    #pragma unroll
    for (int o = 16; o; o >>= 1) m = fmaxf(m, __shfl_xor_sync(0xffffffffu, m, o));
    if ((threadIdx.x & 31) == 0) atomicMax(&g_absmax[which], __float_as_uint(m));
}
__global__ void quant_k(const float* __restrict__ W, float* __restrict__ Q, int n, int which) {
    float scale = fmaxf(__fdiv_rn(__uint_as_float(g_absmax[which]), 7.0f), 1e-8f);
    int i = blockIdx.x*blockDim.x + threadIdx.x;
    if (i < n) Q[i] = __fmul_rn(rintf(__fdiv_rn(W[i], scale)), scale);
}
__global__ void convT_k(const float* __restrict__ convW) {
    int idx = blockIdx.x*blockDim.x + threadIdx.x;
    if (idx >= RED_*KC_) return;
    int o = idx / KC_, rem = idx % KC_;
    int k = rem >> 8, i = rem & 255;
    g_convWt[idx] = convW[o*KC_ + i*5 + k];
}

// ---------------- FFMA2 double-buffered SGEMM 128x128x16 (exact fp32) ----------------
// C = relu(A @ B^T + bias). CONV=1: A is virtual im2col of g_xp (6400 x 1280).
template<int CONV>
__device__ __forceinline__ float4 ldA(const float* __restrict__ A, int K, int row, int c) {
    if (CONV) {
        int tap = c >> 8, chn = c & 255;
        int b = row / T_, t = row - b*T_;
        int ts = t + tap - 2;
        if (ts < 0 || ts >= T_) return make_float4(0,0,0,0);
        return *reinterpret_cast<const float4*>(A + (size_t)(b*T_ + ts)*RED_ + chn);
    } else {
        if (c >= K) return make_float4(0,0,0,0);
        return *reinterpret_cast<const float4*>(A + (size_t)row*K + c);
    }
}

template<int CONV>
__global__ __launch_bounds__(256, 2)
void sgemm_k(const float* __restrict__ A, const float* __restrict__ B,
             const float* __restrict__ bias, float* __restrict__ C,
             int K, int N)
{
    __shared__ float sA[2][16][128];
    __shared__ float sB[2][16][128];

    const int tid  = threadIdx.x;
    const int lane = tid & 31;
    const int wid  = tid >> 5;
    const int lr   = lane >> 2;
    const int lc   = lane & 3;
    const int wm   = (wid & 1) * 64;
    const int wn   = (wid >> 1) * 32;
    const int bm0  = blockIdx.y * 128, bn0 = blockIdx.x * 128;

    unsigned long long acc2[2][2][4][2];
    #pragma unroll
    for (int im = 0; im < 2; ++im)
        #pragma unroll
        for (int in = 0; in < 2; ++in)
            #pragma unroll
            for (int i = 0; i < 4; ++i) {
                acc2[im][in][i][0] = 0ull;
                acc2[im][in][i][1] = 0ull;
            }

    const int nch = (K + 15) >> 4;
    float4 va[2], vb[2];

    {   // prologue chunk 0
        #pragma unroll
        for (int i = 0; i < 2; ++i) {
            int q = tid + 256*i;
            int row = q >> 2, c = (q & 3) * 4;
            va[i] = ldA<CONV>(A, K, bm0 + row, c);
            vb[i] = (c < K) ? *reinterpret_cast<const float4*>(B + (size_t)(bn0+row)*K + c)
                            : make_float4(0,0,0,0);
        }
        #pragma unroll
        for (int i = 0; i < 2; ++i) {
            int q = tid + 256*i;
            int row = q >> 2, c4 = (q & 3) * 4;
            sA[0][c4+0][row] = va[i].x; sA[0][c4+1][row] = va[i].y;
            sA[0][c4+2][row] = va[i].z; sA[0][c4+3][row] = va[i].w;
            sB[0][c4+0][row] = vb[i].x; sB[0][c4+1][row] = vb[i].y;
            sB[0][c4+2][row] = vb[i].z; sB[0][c4+3][row] = vb[i].w;
        }
        __syncthreads();
    }

    int p = 0;
    for (int ch = 0; ch < nch; ++ch) {
        const bool more = (ch + 1 < nch);
        if (more) {
            int k0 = (ch + 1) * 16;
            #pragma unroll
            for (int i = 0; i < 2; ++i) {
                int q = tid + 256*i;
                int row = q >> 2, c = k0 + (q & 3) * 4;
                va[i] = ldA<CONV>(A, K, bm0 + row, c);
                vb[i] = (c < K) ? *reinterpret_cast<const float4*>(B + (size_t)(bn0+row)*K + c)
                                : make_float4(0,0,0,0);
            }
        }
        #pragma unroll
        for (int kk = 0; kk < 16; ++kk) {
            float4 a0 = *reinterpret_cast<const float4*>(&sA[p][kk][wm + lr*4]);
            float4 a1 = *reinterpret_cast<const float4*>(&sA[p][kk][wm + 32 + lr*4]);
            ulonglong2 b0 = *reinterpret_cast<const ulonglong2*>(&sB[p][kk][wn + lc*4]);
            ulonglong2 b1 = *reinterpret_cast<const ulonglong2*>(&sB[p][kk][wn + 16 + lc*4]);
            unsigned long long bp[2][2] = { { b0.x, b0.y }, { b1.x, b1.y } };
            const float av[2][4] = { { a0.x, a0.y, a0.z, a0.w },
                                     { a1.x, a1.y, a1.z, a1.w } };
            #pragma unroll
            for (int im = 0; im < 2; ++im)
                #pragma unroll
                for (int i = 0; i < 4; ++i) {
                    unsigned long long ad = dup_f32x2(av[im][i]);
                    #pragma unroll
                    for (int in = 0; in < 2; ++in) {
                        ffma2(acc2[im][in][i][0], ad, bp[in][0]);
                        ffma2(acc2[im][in][i][1], ad, bp[in][1]);
                    }
                }
        }
        if (more) {
            int q2 = p ^ 1;
            #pragma unroll
            for (int i = 0; i < 2; ++i) {
                int q = tid + 256*i;
                int row = q >> 2, c4 = (q & 3) * 4;
                sA[q2][c4+0][row] = va[i].x; sA[q2][c4+1][row] = va[i].y;
                sA[q2][c4+2][row] = va[i].z; sA[q2][c4+3][row] = va[i].w;
                sB[q2][c4+0][row] = vb[i].x; sB[q2][c4+1][row] = vb[i].y;
                sB[q2][c4+2][row] = vb[i].z; sB[q2][c4+3][row] = vb[i].w;
            }
            __syncthreads();
            p = q2;
        }
    }

    #pragma unroll
    for (int im = 0; im < 2; ++im)
        #pragma unroll
        for (int i = 0; i < 4; ++i) {
            int row = bm0 + wm + im*32 + lr*4 + i;
            #pragma unroll
            for (int in = 0; in < 2; ++in) {
                int col = bn0 + wn + in*16 + lc*4;
                float2 p01 = unpack_f32x2(acc2[im][in][i][0]);
                float2 p23 = unpack_f32x2(acc2[im][in][i][1]);
                float4 v;
                v.x = fmaxf(p01.x + __ldg(bias + col + 0), 0.0f);
                v.y = fmaxf(p01.y + __ldg(bias + col + 1), 0.0f);
                v.z = fmaxf(p23.x + __ldg(bias + col + 2), 0.0f);
                v.w = fmaxf(p23.y + __ldg(bias + col + 3), 0.0f);
                *reinterpret_cast<float4*>(C + (size_t)row*N + col) = v;
            }
        }
}

// ---------------- GEMM2: 3-term tf32 mma + drive/spike + borderline flagging ----------
// BM=128, BN=64, BK=32 (stride 36), 256 thr = 8 warps (4x2), warp tile 32x32.
#define PLANE_A (128*36)
#define PLANE_B (64*36)
#define G2_SMEM ((2*PLANE_A + 2*PLANE_B)*4)   // 55296 B

__global__ __launch_bounds__(256, 2)
void g2tf_k(const float* __restrict__ A, const float* __restrict__ B,
            const float* __restrict__ bias,
            const float* __restrict__ latent, const float* __restrict__ gainp,
            float* __restrict__ drv, float* __restrict__ spk)
{
    extern __shared__ float smf[];
    float* sAhi = smf;
    float* sAlo = sAhi + PLANE_A;
    float* sBhi = sAlo + PLANE_A;
    float* sBlo = sBhi + PLANE_B;

    const int tid  = threadIdx.x;
    const int lane = tid & 31;
    const int wid  = tid >> 5;
    const int wm   = (wid & 3) * 32;
    const int wn   = (wid >> 2) * 32;
    const int bm0  = blockIdx.y * 128, bn0 = blockIdx.x * 64;
    const int K = RED_;

    float acc[2][4][4];
    #pragma unroll
    for (int mi = 0; mi < 2; ++mi)
        #pragma unroll
        for (int ni = 0; ni < 4; ++ni)
            #pragma unroll
            for (int q = 0; q < 4; ++q) acc[mi][ni][q] = 0.0f;

    for (int ch = 0; ch < K/32; ++ch) {
        const int k0 = ch * 32;
        float4 va[4], vb[2];
        #pragma unroll
        for (int i = 0; i < 4; ++i) {
            int q = tid + 256*i;
            int row = q >> 3, c = k0 + (q & 7)*4;
            va[i] = *reinterpret_cast<const float4*>(A + (size_t)(bm0+row)*K + c);
        }
        #pragma unroll
        for (int i = 0; i < 2; ++i) {
            int q = tid + 256*i;
            int row = q >> 3, c = k0 + (q & 7)*4;
            vb[i] = *reinterpret_cast<const float4*>(B + (size_t)(bn0+row)*K + c);
        }
        __syncthreads();
        #pragma unroll
        for (int i = 0; i < 4; ++i) {
            int q = tid + 256*i;
            int row = q >> 3, c4 = (q & 7)*4;
            float4 h, l;
            h.x = tf32_hi(va[i].x); l.x = tf32_hi(va[i].x - h.x);
            h.y = tf32_hi(va[i].y); l.y = tf32_hi(va[i].y - h.y);
            h.z = tf32_hi(va[i].z); l.z = tf32_hi(va[i].z - h.z);
            h.w = tf32_hi(va[i].w); l.w = tf32_hi(va[i].w - h.w);
            *reinterpret_cast<float4*>(sAhi + row*36 + c4) = h;
            *reinterpret_cast<float4*>(sAlo + row*36 + c4) = l;
        }
        #pragma unroll
        for (int i = 0; i < 2; ++i) {
            int q = tid + 256*i;
            int row = q >> 3, c4 = (q & 7)*4;
            float4 h, l;
            h.x = tf32_hi(vb[i].x); l.x = tf32_hi(vb[i].x - h.x);
            h.y = tf32_hi(vb[i].y); l.y = tf32_hi(vb[i].y - h.y);
            h.z = tf32_hi(vb[i].z); l.z = tf32_hi(vb[i].z - h.z);
            h.w = tf32_hi(vb[i].w); l.w = tf32_hi(vb[i].w - h.w);
            *reinterpret_cast<float4*>(sBhi + row*36 + c4) = h;
            *reinterpret_cast<float4*>(sBlo + row*36 + c4) = l;
        }
        __syncthreads();
        #pragma unroll
        for (int ks = 0; ks < 4; ++ks) {
            const int bc = ks*8 + (lane & 3);
            const int ar = wm + (lane >> 2);
            float ah[2][4], al[2][4];
            #pragma unroll
            for (int mi = 0; mi < 2; ++mi) {
                int r = ar + mi*16;
                ah[mi][0] = sAhi[r*36 + bc];     ah[mi][1] = sAhi[(r+8)*36 + bc];
                ah[mi][2] = sAhi[r*36 + bc + 4]; ah[mi][3] = sAhi[(r+8)*36 + bc + 4];
                al[mi][0] = sAlo[r*36 + bc];     al[mi][1] = sAlo[(r+8)*36 + bc];
                al[mi][2] = sAlo[r*36 + bc + 4]; al[mi][3] = sAlo[(r+8)*36 + bc + 4];
            }
            float bh[4][2], bl[4][2];
            #pragma unroll
            for (int ni = 0; ni < 4; ++ni) {
                int n = wn + ni*8 + (lane >> 2);
                bh[ni][0] = sBhi[n*36 + bc]; bh[ni][1] = sBhi[n*36 + bc + 4];
                bl[ni][0] = sBlo[n*36 + bc]; bl[ni][1] = sBlo[n*36 + bc + 4];
            }
            #pragma unroll
            for (int mi = 0; mi < 2; ++mi)
                #pragma unroll
                for (int ni = 0; ni < 4; ++ni) {
                    MMA_TF32(acc[mi][ni], ah[mi], bh[ni]);
                    MMA_TF32(acc[mi][ni], ah[mi], bl[ni]);
                    MMA_TF32(acc[mi][ni], al[mi], bh[ni]);
                }
        }
    }

    // epilogue: drive + spike + borderline flag
    const int r0 = bm0 + wm + (lane >> 2);
    const int c0 = bn0 + wn + (lane & 3)*2;
    const float gabs = fabsf(gainp[0]);

    #pragma unroll
    for (int mi = 0; mi < 2; ++mi)
        #pragma unroll
        for (int ni = 0; ni < 4; ++ni) {
            int col = c0 + ni*8;
            float b0 = __ldg(bias + col), b1 = __ldg(bias + col + 1);
            #pragma unroll
            for (int h = 0; h < 2; ++h) {
                int row = r0 + mi*16 + h*8;
                float lat = __ldg(latent + (row % T_));
                float2 dv, sv;
                #pragma unroll
                for (int q = 0; q < 2; ++q) {
                    float pre = acc[mi][ni][h*2+q] + (q ? b1 : b0);
                    float spl = fmaxf(pre, 0.0f) + log1pf(expf(-fabsf(pre)));
                    float d   = (spl * lat) * gabs;
                    unsigned idx = (unsigned)row * (unsigned)WID_ + (unsigned)(col + q);
                    unsigned bits = rbits32(idx);
                    float u = __uint_as_float((bits >> 9) | 0x3f800000u) - 1.0f;
                    float logu = logf(u);
                    float spike = (d >= 10.0f) ? 1.0f : ((logu > -d) ? 1.0f : 0.0f);
                    if (d < 10.0f && fabsf(logu + d) < MARGIN) {
                        unsigned w = atomicAdd(&g_count, 1u);
                        if (w < WCAP) g_worklist[w] = idx;
                    }
                    if (q) { dv.y = d; sv.y = spike; } else { dv.x = d; sv.x = spike; }
                }
                size_t ob = (size_t)row * WID_ + col;
                *reinterpret_cast<float2*>(drv + ob) = dv;
                *reinterpret_cast<float2*>(spk + ob) = sv;
            }
        }
}

// ---------------- exact fp32 fixup for borderline spikes ----------------
__global__ void fixup_k(const float* __restrict__ co, const float* __restrict__ qfc1,
                        const float* __restrict__ bias, const float* __restrict__ latent,
                        const float* __restrict__ gainp, float* __restrict__ spk)
{
    __shared__ float red[4];
    const unsigned n = (g_count < WCAP) ? g_count : WCAP;
    const float gabs = fabsf(gainp[0]);
    const int tid = threadIdx.x;   // 128
    for (unsigned i = blockIdx.x; i < n; i += gridDim.x) {
        unsigned idx = g_worklist[i];
        int row = idx >> 12, col = idx & (WID_-1);
        const float* cr = co + (size_t)row * RED_;
        const float* wr = qfc1 + (size_t)col * RED_;
        float s = cr[tid]*wr[tid] + cr[tid+128]*wr[tid+128];
        #pragma unroll
        for (int o = 16; o; o >>= 1) s += __shfl_xor_sync(0xffffffffu, s, o);
        if ((tid & 31) == 0) red[tid >> 5] = s;
        __syncthreads();
        if (tid == 0) {
            float pre = (red[0]+red[1]) + (red[2]+red[3]) + bias[col];
            float spl = fmaxf(pre, 0.0f) + log1pf(expf(-fabsf(pre)));
            float d   = (spl * latent[row % T_]) * gabs;
            unsigned bits = rbits32(idx);
            float u = __uint_as_float((bits >> 9) | 0x3f800000u) - 1.0f;
            spk[idx] = (d >= 10.0f) ? 1.0f : ((logf(u) > -d) ? 1.0f : 0.0f);
        }
        __syncthreads();
    }
}

// ---------------- decay-weighted temporal reduction ----------------
__global__ void weighted_k(const float* __restrict__ spikes) {
    __shared__ float decay[T_];
    int tid = threadIdx.x;
    if (tid < T_) decay[tid] = expf(-2.0f + (float)tid * (2.0f/99.0f));
    __syncthreads();
    int idx = blockIdx.x * blockDim.x + tid;
    if (idx >= B_*WID_) return;
    int b = idx >> 12, w = idx & (WID_-1);
    const float* sp = spikes + (size_t)b*T_*WID_ + w;
    float s = 0.0f;
    #pragma unroll 4
    for (int t = 0; t < T_; ++t) s += sp[(size_t)t*WID_] * decay[t];
    g_wsum[idx] = s;
}

// ---------------- logits ----------------
__global__ void logits_k(const float* __restrict__ bias, float* __restrict__ out) {
    int bc = blockIdx.x;
    int b = bc / CLS_, c = bc % CLS_;
    const float* wr = g_wsum + (size_t)b*WID_;
    const float* fr = g_qfc2 + (size_t)c*WID_;
    float s = 0.0f;
    for (int i = threadIdx.x; i < WID_; i += 128) s += wr[i]*fr[i];
    #pragma unroll
    for (int o = 16; o; o >>= 1) s += __shfl_xor_sync(0xffffffffu, s, o);
    __shared__ float red[4];
    if ((threadIdx.x & 31) == 0) red[threadIdx.x >> 5] = s;
    __syncthreads();
    if (threadIdx.x == 0) out[bc] = (red[0]+red[1]+red[2]+red[3]) + bias[c];
}

// ---------------- launcher ----------------
extern "C" void kernel_launch(void* const* d_in, const int* in_sizes, int n_in,
                              void* d_out, int out_size) {
    (void)in_sizes; (void)n_in; (void)out_size;
    const float* x        = (const float*)d_in[0];
    const float* latent   = (const float*)d_in[1];
    const float* spatialW = (const float*)d_in[2];
    const float* spatialB = (const float*)d_in[3];
    const float* convW    = (const float*)d_in[4];
    const float* convB    = (const float*)d_in[5];
    const float* fc1W     = (const float*)d_in[6];
    const float* fc1B     = (const float*)d_in[7];
    const float* fc2W     = (const float*)d_in[8];
    const float* fc2B     = (const float*)d_in[9];
    const float* gain     = (const float*)d_in[10];

    float* out        = (float*)d_out;
    float* out_logits = out;
    float* out_spk    = out + (CLS_*B_);
    float* out_drv    = out + (CLS_*B_) + (size_t)NELEM_;

    float *qsp, *qfc1, *qfc2, *cwt, *xp, *co;
    cudaGetSymbolAddress((void**)&qsp,  g_qsp);
    cudaGetSymbolAddress((void**)&qfc1, g_qfc1);
    cudaGetSymbolAddress((void**)&qfc2, g_qfc2);
    cudaGetSymbolAddress((void**)&cwt,  g_convWt);
    cudaGetSymbolAddress((void**)&xp,   g_xp);
    cudaGetSymbolAddress((void**)&co,   g_co);

    static bool attr_set = false;
    if (!attr_set) {
        cudaFuncSetAttribute(g2tf_k, cudaFuncAttributeMaxDynamicSharedMemorySize, G2_SMEM);
        attr_set = true;
    }

    init_k<<<1, 32>>>();
    absmax_k<<<128, 256>>>(spatialW, RED_*INF_,  0);
    absmax_k<<<256, 256>>>(fc1W,     WID_*RED_,  1);
    absmax_k<<<128, 256>>>(fc2W,     CLS_*WID_,  2);
    quant_k<<<(RED_*INF_ + 255)/256, 256>>>(spatialW, qsp,  RED_*INF_, 0);
    quant_k<<<(WID_*RED_ + 255)/256, 256>>>(fc1W,     qfc1, WID_*RED_, 1);
    quant_k<<<(CLS_*WID_ + 255)/256, 256>>>(fc2W,     qfc2, CLS_*WID_, 2);
    convT_k<<<(RED_*KC_ + 255)/256, 256>>>(convW);

    // GEMM1: xp = relu(x @ qsp^T + b)   M=6400 N=256 K=700  (exact fp32)
    sgemm_k<0><<<dim3(RED_/128, ROWS_/128), 256>>>(x, qsp, spatialB, xp, INF_, RED_);
    // conv (fused im2col): co = relu(im2col(xp) @ cwt^T + cb)  K=1280  (exact fp32)
    sgemm_k<1><<<dim3(RED_/128, ROWS_/128), 256>>>(xp, cwt, convB, co, KC_, RED_);
    // GEMM2 (tf32 3-term) + drive/spike + flags
    g2tf_k<<<dim3(WID_/64, ROWS_/128), 256, G2_SMEM>>>(co, qfc1, fc1B,
                                                       latent, gain, out_drv, out_spk);
    // exact recompute of borderline spikes
    fixup_k<<<1024, 128>>>(co, qfc1, fc1B, latent, gain, out_spk);
    weighted_k<<<(B_*WID_ + 255)/256, 256>>>(out_spk);
    logits_k<<<B_*CLS_, 128>>>(fc2B, out_logits);
}

// round 9
// speedup vs baseline: 1.2900x; 1.0344x over previous
#include <cuda_runtime.h>
#include <cstdint>

// ---------------- problem dims ----------------
#define B_    64
#define T_    100
#define INF_  700
#define RED_  256
#define WID_  4096
#define CLS_  20
#define ROWS_ (B_*T_)          // 6400
#define KC_   1280             // conv im2col K (256*5)
#define NELEM_ (ROWS_*WID_)    // 26214400
#define WCAP  (1u<<22)
#define MARGIN 7e-4f

// ---------------- scratch (static device globals; no alloc allowed) ----------------
__device__ unsigned g_absmax[4];
__device__ unsigned g_count;
__device__ unsigned g_worklist[WCAP];
__device__ float  g_qsp[RED_*INF_];
__device__ float  g_qfc1[WID_*RED_];      // exact (fixup)
__device__ float2 g_qfc1s[WID_*RED_];     // {tf32 hi, tf32 lo}
__device__ float  g_qfc2[CLS_*WID_];
__device__ float  g_convWt[RED_*KC_];
__device__ float  g_xp[ROWS_*RED_];
__device__ float  g_co[ROWS_*RED_];       // exact (fixup)
__device__ float2 g_co2[ROWS_*RED_];      // {hi, lo}
__device__ float  g_wsum[B_*WID_];

// ---------------- threefry2x32 (JAX-compatible, partitionable mode) ----------------
__host__ __device__ constexpr unsigned rotl32c(unsigned v, int s) {
    return (v << s) | (v >> (32 - s));
}
struct K2 { unsigned a, b; };
constexpr K2 tf_const(unsigned k0, unsigned k1, unsigned x0, unsigned x1) {
    unsigned ks2 = k0 ^ k1 ^ 0x1BD11BDAu;
    unsigned ks[3] = {k0, k1, ks2};
    x0 += k0; x1 += k1;
    const int R[20] = {13,15,26,6, 17,29,16,24, 13,15,26,6, 17,29,16,24, 13,15,26,6};
    for (int g = 0; g < 5; ++g) {
        for (int j = 0; j < 4; ++j) { x0 += x1; x1 = rotl32c(x1, R[g*4+j]); x1 ^= x0; }
        x0 += ks[(g+1)%3];
        x1 += ks[(g+2)%3] + (unsigned)(g+1);
    }
    return K2{x0, x1};
}
constexpr K2 SUBKEY = tf_const(0u, 42u, 0u, 1u);
constexpr unsigned SK0 = SUBKEY.a;
constexpr unsigned SK1 = SUBKEY.b;

__device__ __forceinline__ uint2 tf2x32(unsigned k0, unsigned k1, unsigned x0, unsigned x1) {
    unsigned ks2 = k0 ^ k1 ^ 0x1BD11BDAu;
    x0 += k0; x1 += k1;
#define TFR(r) { x0 += x1; x1 = __funnelshift_l(x1, x1, (r)); x1 ^= x0; }
    TFR(13) TFR(15) TFR(26) TFR(6)   x0 += k1;  x1 += ks2 + 1u;
    TFR(17) TFR(29) TFR(16) TFR(24)  x0 += ks2; x1 += k0  + 2u;
    TFR(13) TFR(15) TFR(26) TFR(6)   x0 += k0;  x1 += k1  + 3u;
    TFR(17) TFR(29) TFR(16) TFR(24)  x0 += k1;  x1 += ks2 + 4u;
    TFR(13) TFR(15) TFR(26) TFR(6)   x0 += ks2; x1 += k0  + 5u;
#undef TFR
    return make_uint2(x0, x1);
}
__device__ __forceinline__ unsigned rbits32(unsigned idx) {
    uint2 r = tf2x32(SK0, SK1, 0u, idx);
    return r.x ^ r.y;
}

// ---------------- packed f32x2 helpers ----------------
__device__ __forceinline__ void ffma2(unsigned long long& acc,
                                      unsigned long long a,
                                      unsigned long long b) {
    asm("fma.rn.f32x2 %0, %1, %2, %0;" : "+l"(acc) : "l"(a), "l"(b));
}
__device__ __forceinline__ unsigned long long dup_f32x2(float x) {
    unsigned long long d;
    asm("mov.b64 %0, {%1, %1};" : "=l"(d) : "f"(x));
    return d;
}
__device__ __forceinline__ float2 unpack_f32x2(unsigned long long v) {
    float lo, hi;
    asm("mov.b64 {%0, %1}, %2;" : "=f"(lo), "=f"(hi) : "l"(v));
    return make_float2(lo, hi);
}

// ---------------- tf32 helpers ----------------
__device__ __forceinline__ float tf32_hi(float x) {
    uint32_t u; asm("cvt.rna.tf32.f32 %0, %1;" : "=r"(u) : "f"(x));
    return __uint_as_float(u);
}
#define MMA_TF32(c, a, b) \
    asm volatile("mma.sync.aligned.m16n8k8.row.col.f32.tf32.tf32.f32 " \
        "{%0,%1,%2,%3}, {%4,%5,%6,%7}, {%8,%9}, {%0,%1,%2,%3};" \
        : "+f"((c)[0]), "+f"((c)[1]), "+f"((c)[2]), "+f"((c)[3]) \
        : "r"(__float_as_uint((a)[0])), "r"(__float_as_uint((a)[1])), \
          "r"(__float_as_uint((a)[2])), "r"(__float_as_uint((a)[3])), \
          "r"(__float_as_uint((b)[0])), "r"(__float_as_uint((b)[1])))

__device__ __forceinline__ uint32_t smem_u32(const void* p) {
    uint32_t a;
    asm("{ .reg .u64 t; cvta.to.shared.u64 t, %1; cvt.u32.u64 %0, t; }" : "=r"(a) : "l"(p));
    return a;
}
#define CP_ASYNC16(s, g) \
    asm volatile("cp.async.cg.shared.global [%0], [%1], 16;" :: "r"(s), "l"(g))
#define CP_COMMIT()  asm volatile("cp.async.commit_group;")
#define CP_WAIT0()   asm volatile("cp.async.wait_group 0;")

// ---------------- small kernels ----------------
__global__ void init_k() {
    if (threadIdx.x < 4) g_absmax[threadIdx.x] = 0u;
    if (threadIdx.x == 0) g_count = 0u;
}
__global__ void absmax_k(const float* __restrict__ W, int n, int which) {
    float m = 0.0f;
    for (int i = blockIdx.x*blockDim.x + threadIdx.x; i < n; i += gridDim.x*blockDim.x)
        m = fmaxf(m, fabsf(W[i]));
    #pragma unroll
    for (int o = 16; o; o >>= 1) m = fmaxf(m, __shfl_xor_sync(0xffffffffu, m, o));
    if ((threadIdx.x & 31) == 0) atomicMax(&g_absmax[which], __float_as_uint(m));
}
__global__ void quant_k(const float* __restrict__ W, float* __restrict__ Q, int n, int which) {
    float scale = fmaxf(__fdiv_rn(__uint_as_float(g_absmax[which]), 7.0f), 1e-8f);
    int i = blockIdx.x*blockDim.x + threadIdx.x;
    if (i < n) Q[i] = __fmul_rn(rintf(__fdiv_rn(W[i], scale)), scale);
}
// quant + tf32 hi/lo split (for fc1W)
__global__ void quant_split_k(const float* __restrict__ W, float* __restrict__ Q,
                              float2* __restrict__ Qs, int n, int which) {
    float scale = fmaxf(__fdiv_rn(__uint_as_float(g_absmax[which]), 7.0f), 1e-8f);
    int i = blockIdx.x*blockDim.x + threadIdx.x;
    if (i < n) {
        float q = __fmul_rn(rintf(__fdiv_rn(W[i], scale)), scale);
        Q[i] = q;
        float hi = tf32_hi(q);
        float lo = tf32_hi(q - hi);
        Qs[i] = make_float2(hi, lo);
    }
}
__global__ void convT_k(const float* __restrict__ convW) {
    int idx = blockIdx.x*blockDim.x + threadIdx.x;
    if (idx >= RED_*KC_) return;
    int o = idx / KC_, rem = idx % KC_;
    int k = rem >> 8, i = rem & 255;
    g_convWt[idx] = convW[o*KC_ + i*5 + k];
}

// ---------------- FFMA2 double-buffered SGEMM 128x128x16 (exact fp32) ----------------
template<int CONV>
__device__ __forceinline__ float4 ldA(const float* __restrict__ A, int K, int row, int c) {
    if (CONV) {
        int tap = c >> 8, chn = c & 255;
        int b = row / T_, t = row - b*T_;
        int ts = t + tap - 2;
        if (ts < 0 || ts >= T_) return make_float4(0,0,0,0);
        return *reinterpret_cast<const float4*>(A + (size_t)(b*T_ + ts)*RED_ + chn);
    } else {
        if (c >= K) return make_float4(0,0,0,0);
        return *reinterpret_cast<const float4*>(A + (size_t)row*K + c);
    }
}

template<int CONV, int SPLIT>
__global__ __launch_bounds__(256, 2)
void sgemm_k(const float* __restrict__ A, const float* __restrict__ B,
             const float* __restrict__ bias, float* __restrict__ C,
             float2* __restrict__ Cs, int K, int N)
{
    __shared__ float sA[2][16][128];
    __shared__ float sB[2][16][128];

    const int tid  = threadIdx.x;
    const int lane = tid & 31;
    const int wid  = tid >> 5;
    const int lr   = lane >> 2;
    const int lc   = lane & 3;
    const int wm   = (wid & 1) * 64;
    const int wn   = (wid >> 1) * 32;
    const int bm0  = blockIdx.y * 128, bn0 = blockIdx.x * 128;

    unsigned long long acc2[2][2][4][2];
    #pragma unroll
    for (int im = 0; im < 2; ++im)
        #pragma unroll
        for (int in = 0; in < 2; ++in)
            #pragma unroll
            for (int i = 0; i < 4; ++i) {
                acc2[im][in][i][0] = 0ull;
                acc2[im][in][i][1] = 0ull;
            }

    const int nch = (K + 15) >> 4;
    float4 va[2], vb[2];

    {
        #pragma unroll
        for (int i = 0; i < 2; ++i) {
            int q = tid + 256*i;
            int row = q >> 2, c = (q & 3) * 4;
            va[i] = ldA<CONV>(A, K, bm0 + row, c);
            vb[i] = (c < K) ? *reinterpret_cast<const float4*>(B + (size_t)(bn0+row)*K + c)
                            : make_float4(0,0,0,0);
        }
        #pragma unroll
        for (int i = 0; i < 2; ++i) {
            int q = tid + 256*i;
            int row = q >> 2, c4 = (q & 3) * 4;
            sA[0][c4+0][row] = va[i].x; sA[0][c4+1][row] = va[i].y;
            sA[0][c4+2][row] = va[i].z; sA[0][c4+3][row] = va[i].w;
            sB[0][c4+0][row] = vb[i].x; sB[0][c4+1][row] = vb[i].y;
            sB[0][c4+2][row] = vb[i].z; sB[0][c4+3][row] = vb[i].w;
        }
        __syncthreads();
    }

    int p = 0;
    for (int ch = 0; ch < nch; ++ch) {
        const bool more = (ch + 1 < nch);
        if (more) {
            int k0 = (ch + 1) * 16;
            #pragma unroll
            for (int i = 0; i < 2; ++i) {
                int q = tid + 256*i;
                int row = q >> 2, c = k0 + (q & 3) * 4;
                va[i] = ldA<CONV>(A, K, bm0 + row, c);
                vb[i] = (c < K) ? *reinterpret_cast<const float4*>(B + (size_t)(bn0+row)*K + c)
                                : make_float4(0,0,0,0);
            }
        }
        #pragma unroll
        for (int kk = 0; kk < 16; ++kk) {
            float4 a0 = *reinterpret_cast<const float4*>(&sA[p][kk][wm + lr*4]);
            float4 a1 = *reinterpret_cast<const float4*>(&sA[p][kk][wm + 32 + lr*4]);
            ulonglong2 b0 = *reinterpret_cast<const ulonglong2*>(&sB[p][kk][wn + lc*4]);
            ulonglong2 b1 = *reinterpret_cast<const ulonglong2*>(&sB[p][kk][wn + 16 + lc*4]);
            unsigned long long bp[2][2] = { { b0.x, b0.y }, { b1.x, b1.y } };
            const float av[2][4] = { { a0.x, a0.y, a0.z, a0.w },
                                     { a1.x, a1.y, a1.z, a1.w } };
            #pragma unroll
            for (int im = 0; im < 2; ++im)
                #pragma unroll
                for (int i = 0; i < 4; ++i) {
                    unsigned long long ad = dup_f32x2(av[im][i]);
                    #pragma unroll
                    for (int in = 0; in < 2; ++in) {
                        ffma2(acc2[im][in][i][0], ad, bp[in][0]);
                        ffma2(acc2[im][in][i][1], ad, bp[in][1]);
                    }
                }
        }
        if (more) {
            int q2 = p ^ 1;
            #pragma unroll
            for (int i = 0; i < 2; ++i) {
                int q = tid + 256*i;
                int row = q >> 2, c4 = (q & 3) * 4;
                sA[q2][c4+0][row] = va[i].x; sA[q2][c4+1][row] = va[i].y;
                sA[q2][c4+2][row] = va[i].z; sA[q2][c4+3][row] = va[i].w;
                sB[q2][c4+0][row] = vb[i].x; sB[q2][c4+1][row] = vb[i].y;
                sB[q2][c4+2][row] = vb[i].z; sB[q2][c4+3][row] = vb[i].w;
            }
            __syncthreads();
            p = q2;
        }
    }

    #pragma unroll
    for (int im = 0; im < 2; ++im)
        #pragma unroll
        for (int i = 0; i < 4; ++i) {
            int row = bm0 + wm + im*32 + lr*4 + i;
            #pragma unroll
            for (int in = 0; in < 2; ++in) {
                int col = bn0 + wn + in*16 + lc*4;
                float2 p01 = unpack_f32x2(acc2[im][in][i][0]);
                float2 p23 = unpack_f32x2(acc2[im][in][i][1]);
                float4 v;
                v.x = fmaxf(p01.x + __ldg(bias + col + 0), 0.0f);
                v.y = fmaxf(p01.y + __ldg(bias + col + 1), 0.0f);
                v.z = fmaxf(p23.x + __ldg(bias + col + 2), 0.0f);
                v.w = fmaxf(p23.y + __ldg(bias + col + 3), 0.0f);
                *reinterpret_cast<float4*>(C + (size_t)row*N + col) = v;
                if (SPLIT) {
                    const float* vf = &v.x;
                    float4 s01, s23;
                    float* sp01 = &s01.x; float* sp23 = &s23.x;
                    #pragma unroll
                    for (int q = 0; q < 2; ++q) {
                        float hi = tf32_hi(vf[q]);
                        sp01[q*2+0] = hi; sp01[q*2+1] = tf32_hi(vf[q] - hi);
                    }
                    #pragma unroll
                    for (int q = 2; q < 4; ++q) {
                        float hi = tf32_hi(vf[q]);
                        sp23[(q-2)*2+0] = hi; sp23[(q-2)*2+1] = tf32_hi(vf[q] - hi);
                    }
                    *reinterpret_cast<float4*>(Cs + (size_t)row*N + col)     = s01;
                    *reinterpret_cast<float4*>(Cs + (size_t)row*N + col + 2) = s23;
                }
            }
        }
}

// ---------------- GEMM2: pre-split tf32 3-term mma, cp.async double-buffered ----------
// BM=128, BN=64, BK=16 (16 chunks of K=256), 8 warps (4x2), warp tile 32x32.
#define AST 20                         // padded k-stride in float2
#define ASZ (128*AST)                  // A buffer, float2
#define BSZ (64*AST)                   // B buffer, float2
#define G2_SMEM ((2*ASZ + 2*BSZ)*8)    // 61440 B

__device__ __forceinline__ void g2_issue(const float2* __restrict__ co2,
                                         const float2* __restrict__ qfc1s,
                                         uint32_t sAa, uint32_t sBa,
                                         int bm0, int bn0, int k0, int tid) {
    #pragma unroll
    for (int i = 0; i < 4; ++i) {
        int cid = tid + 256*i;
        int row = cid >> 3, kp = (cid & 7) * 2;
        const float2* g = co2 + (size_t)(bm0+row)*RED_ + k0 + kp;
        CP_ASYNC16(sAa + (uint32_t)((row*AST + kp) * 8), g);
    }
    #pragma unroll
    for (int i = 0; i < 2; ++i) {
        int cid = tid + 256*i;
        int row = cid >> 3, kp = (cid & 7) * 2;
        const float2* g = qfc1s + (size_t)(bn0+row)*RED_ + k0 + kp;
        CP_ASYNC16(sBa + (uint32_t)((row*AST + kp) * 8), g);
    }
    CP_COMMIT();
}

__global__ __launch_bounds__(256, 2)
void g2tf_k(const float2* __restrict__ co2, const float2* __restrict__ qfc1s,
            const float* __restrict__ bias,
            const float* __restrict__ latent, const float* __restrict__ gainp,
            float* __restrict__ drv, float* __restrict__ spk)
{
    extern __shared__ float2 smf2[];
    const uint32_t smem_base = smem_u32(smf2);

    const int tid  = threadIdx.x;
    const int lane = tid & 31;
    const int wid  = tid >> 5;
    const int wm   = (wid & 3) * 32;
    const int wn   = (wid >> 2) * 32;
    const int bm0  = blockIdx.y * 128, bn0 = blockIdx.x * 64;

    float acc[2][4][4];
    #pragma unroll
    for (int mi = 0; mi < 2; ++mi)
        #pragma unroll
        for (int ni = 0; ni < 4; ++ni)
            #pragma unroll
            for (int q = 0; q < 4; ++q) acc[mi][ni][q] = 0.0f;

    // prologue: chunk 0 into buffer 0
    g2_issue(co2, qfc1s, smem_base, smem_base + 2*ASZ*8, bm0, bn0, 0, tid);

    #pragma unroll 1
    for (int ch = 0; ch < 16; ++ch) {
        CP_WAIT0();
        __syncthreads();
        const int p = ch & 1;
        if (ch + 1 < 16) {
            const int q2 = p ^ 1;
            g2_issue(co2, qfc1s, smem_base + q2*ASZ*8,
                     smem_base + (2*ASZ + q2*BSZ)*8, bm0, bn0, (ch+1)*16, tid);
        }
        const float2* A2 = smf2 + p*ASZ;
        const float2* B2 = smf2 + 2*ASZ + p*BSZ;
        #pragma unroll
        for (int ksl = 0; ksl < 2; ++ksl) {
            const int bc = ksl*8 + (lane & 3);
            float2 afr[2][4];
            #pragma unroll
            for (int mi = 0; mi < 2; ++mi) {
                int r = wm + (lane >> 2) + mi*16;
                afr[mi][0] = A2[r*AST + bc];
                afr[mi][1] = A2[(r+8)*AST + bc];
                afr[mi][2] = A2[r*AST + bc + 4];
                afr[mi][3] = A2[(r+8)*AST + bc + 4];
            }
            float2 bfr[4][2];
            #pragma unroll
            for (int ni = 0; ni < 4; ++ni) {
                int n = wn + ni*8 + (lane >> 2);
                bfr[ni][0] = B2[n*AST + bc];
                bfr[ni][1] = B2[n*AST + bc + 4];
            }
            #pragma unroll
            for (int mi = 0; mi < 2; ++mi) {
                float ah[4] = { afr[mi][0].x, afr[mi][1].x, afr[mi][2].x, afr[mi][3].x };
                float al[4] = { afr[mi][0].y, afr[mi][1].y, afr[mi][2].y, afr[mi][3].y };
                #pragma unroll
                for (int ni = 0; ni < 4; ++ni) {
                    float bh[2] = { bfr[ni][0].x, bfr[ni][1].x };
                    float bl[2] = { bfr[ni][0].y, bfr[ni][1].y };
                    MMA_TF32(acc[mi][ni], ah, bh);
                    MMA_TF32(acc[mi][ni], ah, bl);
                    MMA_TF32(acc[mi][ni], al, bh);
                }
            }
        }
    }

    // epilogue: fast-math drive + integer-domain spike + borderline flag
    const int r0 = bm0 + wm + (lane >> 2);
    const int c0 = bn0 + wn + (lane & 3)*2;
    const float gabs = fabsf(gainp[0]);

    #pragma unroll
    for (int mi = 0; mi < 2; ++mi)
        #pragma unroll
        for (int ni = 0; ni < 4; ++ni) {
            int col = c0 + ni*8;
            float b0 = __ldg(bias + col), b1 = __ldg(bias + col + 1);
            #pragma unroll
            for (int h = 0; h < 2; ++h) {
                int row = r0 + mi*16 + h*8;
                float lat = __ldg(latent + (row % T_));
                float2 dv, sv;
                #pragma unroll
                for (int q = 0; q < 2; ++q) {
                    float pre = acc[mi][ni][h*2+q] + (q ? b1 : b0);
                    float e   = __expf(-fabsf(pre));
                    float sp  = fmaxf(pre, 0.0f) + __logf(1.0f + e);
                    float d   = (sp * lat) * gabs;
                    unsigned idx = (unsigned)row * (unsigned)WID_ + (unsigned)(col + q);
                    unsigned bits = rbits32(idx);
                    float u = __uint_as_float((bits >> 9) | 0x3f800000u) - 1.0f;
                    float spike;
                    if (d >= 10.0f) spike = 1.0f;
                    else {
                        float t = __expf(-d);
                        spike = (u > t) ? 1.0f : 0.0f;
                        if (fabsf(u - t) < MARGIN * t) {
                            unsigned w = atomicAdd(&g_count, 1u);
                            if (w < WCAP) g_worklist[w] = idx;
                        }
                    }
                    if (q) { dv.y = d; sv.y = spike; } else { dv.x = d; sv.x = spike; }
                }
                size_t ob = (size_t)row * WID_ + col;
                *reinterpret_cast<float2*>(drv + ob) = dv;
                *reinterpret_cast<float2*>(spk + ob) = sv;
            }
        }
}

// ---------------- exact fp32 fixup for borderline spikes (reference semantics) --------
__global__ void fixup_k(const float* __restrict__ co, const float* __restrict__ qfc1,
                        const float* __restrict__ bias, const float* __restrict__ latent,
                        const float* __restrict__ gainp, float* __restrict__ spk)
{
    __shared__ float red[4];
    const unsigned n = (g_count < WCAP) ? g_count : WCAP;
    const float gabs = fabsf(gainp[0]);
    const int tid = threadIdx.x;   // 128
    for (unsigned i = blockIdx.x; i < n; i += gridDim.x) {
        unsigned idx = g_worklist[i];
        int row = idx >> 12, col = idx & (WID_-1);
        const float* cr = co + (size_t)row * RED_;
        const float* wr = qfc1 + (size_t)col * RED_;
        float s = cr[tid]*wr[tid] + cr[tid+128]*wr[tid+128];
        #pragma unroll
        for (int o = 16; o; o >>= 1) s += __shfl_xor_sync(0xffffffffu, s, o);
        if ((tid & 31) == 0) red[tid >> 5] = s;
        __syncthreads();
        if (tid == 0) {
            float pre = (red[0]+red[1]) + (red[2]+red[3]) + bias[col];
            float spl = fmaxf(pre, 0.0f) + log1pf(expf(-fabsf(pre)));
            float d   = (spl * latent[row % T_]) * gabs;
            unsigned bits = rbits32(idx);
            float u = __uint_as_float((bits >> 9) | 0x3f800000u) - 1.0f;
            spk[idx] = (d >= 10.0f) ? 1.0f : ((logf(u) > -d) ? 1.0f : 0.0f);
        }
        __syncthreads();
    }
}

// ---------------- decay-weighted temporal reduction ----------------
__global__ void weighted_k(const float* __restrict__ spikes) {
    __shared__ float decay[T_];
    int tid = threadIdx.x;
    if (tid < T_) decay[tid] = expf(-2.0f + (float)tid * (2.0f/99.0f));
    __syncthreads();
    int idx = blockIdx.x * blockDim.x + tid;
    if (idx >= B_*WID_) return;
    int b = idx >> 12, w = idx & (WID_-1);
    const float* sp = spikes + (size_t)b*T_*WID_ + w;
    float s = 0.0f;
    #pragma unroll 4
    for (int t = 0; t < T_; ++t) s += sp[(size_t)t*WID_] * decay[t];
    g_wsum[idx] = s;
}

// ---------------- logits ----------------
__global__ void logits_k(const float* __restrict__ bias, float* __restrict__ out) {
    int bc = blockIdx.x;
    int b = bc / CLS_, c = bc % CLS_;
    const float* wr = g_wsum + (size_t)b*WID_;
    const float* fr = g_qfc2 + (size_t)c*WID_;
    float s = 0.0f;
    for (int i = threadIdx.x; i < WID_; i += 128) s += wr[i]*fr[i];
    #pragma unroll
    for (int o = 16; o; o >>= 1) s += __shfl_xor_sync(0xffffffffu, s, o);
    __shared__ float red[4];
    if ((threadIdx.x & 31) == 0) red[threadIdx.x >> 5] = s;
    __syncthreads();
    if (threadIdx.x == 0) out[bc] = (red[0]+red[1]+red[2]+red[3]) + bias[c];
}

// ---------------- launcher ----------------
extern "C" void kernel_launch(void* const* d_in, const int* in_sizes, int n_in,
                              void* d_out, int out_size) {
    (void)in_sizes; (void)n_in; (void)out_size;
    const float* x        = (const float*)d_in[0];
    const float* latent   = (const float*)d_in[1];
    const float* spatialW = (const float*)d_in[2];
    const float* spatialB = (const float*)d_in[3];
    const float* convW    = (const float*)d_in[4];
    const float* convB    = (const float*)d_in[5];
    const float* fc1W     = (const float*)d_in[6];
    const float* fc1B     = (const float*)d_in[7];
    const float* fc2W     = (const float*)d_in[8];
    const float* fc2B     = (const float*)d_in[9];
    const float* gain     = (const float*)d_in[10];

    float* out        = (float*)d_out;
    float* out_logits = out;
    float* out_spk    = out + (CLS_*B_);
    float* out_drv    = out + (CLS_*B_) + (size_t)NELEM_;

    float *qsp, *qfc1, *qfc2, *cwt, *xp, *co;
    float2 *qfc1s, *co2;
    cudaGetSymbolAddress((void**)&qsp,   g_qsp);
    cudaGetSymbolAddress((void**)&qfc1,  g_qfc1);
    cudaGetSymbolAddress((void**)&qfc1s, g_qfc1s);
    cudaGetSymbolAddress((void**)&qfc2,  g_qfc2);
    cudaGetSymbolAddress((void**)&cwt,   g_convWt);
    cudaGetSymbolAddress((void**)&xp,    g_xp);
    cudaGetSymbolAddress((void**)&co,    g_co);
    cudaGetSymbolAddress((void**)&co2,   g_co2);

    static bool attr_set = false;
    if (!attr_set) {
        cudaFuncSetAttribute(g2tf_k, cudaFuncAttributeMaxDynamicSharedMemorySize, G2_SMEM);
        attr_set = true;
    }

    init_k<<<1, 32>>>();
    absmax_k<<<128, 256>>>(spatialW, RED_*INF_,  0);
    absmax_k<<<256, 256>>>(fc1W,     WID_*RED_,  1);
    absmax_k<<<128, 256>>>(fc2W,     CLS_*WID_,  2);
    quant_k<<<(RED_*INF_ + 255)/256, 256>>>(spatialW, qsp,  RED_*INF_, 0);
    quant_split_k<<<(WID_*RED_ + 255)/256, 256>>>(fc1W, qfc1, qfc1s, WID_*RED_, 1);
    quant_k<<<(CLS_*WID_ + 255)/256, 256>>>(fc2W,     qfc2, CLS_*WID_, 2);
    convT_k<<<(RED_*KC_ + 255)/256, 256>>>(convW);

    // GEMM1: xp = relu(x @ qsp^T + b)   (exact fp32 FFMA2)
    sgemm_k<0,0><<<dim3(RED_/128, ROWS_/128), 256>>>(x, qsp, spatialB, xp, nullptr, INF_, RED_);
    // conv (fused im2col): co = relu(im2col(xp) @ cwt^T + cb), also emits split co2
    sgemm_k<1,1><<<dim3(RED_/128, ROWS_/128), 256>>>(xp, cwt, convB, co, co2, KC_, RED_);
    // GEMM2 (tf32 3-term, cp.async pipelined) + fast drive/spike + flags
    g2tf_k<<<dim3(WID_/64, ROWS_/128), 256, G2_SMEM>>>(co2, qfc1s, fc1B,
                                                       latent, gain, out_drv, out_spk);
    // exact recompute of borderline spikes
    fixup_k<<<1024, 128>>>(co, qfc1, fc1B, latent, gain, out_spk);
    weighted_k<<<(B_*WID_ + 255)/256, 256>>>(out_spk);
    logits_k<<<B_*CLS_, 128>>>(fc2B, out_logits);
}

// round 10
// speedup vs baseline: 1.4658x; 1.1363x over previous
#include <cuda_runtime.h>
#include <cstdint>

// ---------------- problem dims ----------------
#define B_    64
#define T_    100
#define INF_  700
#define RED_  256
#define WID_  4096
#define CLS_  20
#define ROWS_ (B_*T_)          // 6400
#define KC_   1280             // conv im2col K (256*5)
#define NELEM_ (ROWS_*WID_)    // 26214400
#define WCAP  (1u<<22)
#define MARGIN 7e-4f

// ---------------- scratch (static device globals; no alloc allowed) ----------------
__device__ unsigned g_absmax[4];
__device__ unsigned g_count;
__device__ unsigned g_worklist[WCAP];
__device__ float  g_qsp[RED_*INF_];
__device__ float  g_qfc1[WID_*RED_];      // exact scale*k (fixup)
__device__ float  g_qk[WID_*RED_];        // integer k as float (tf32-exact)
__device__ float  g_qfc2[CLS_*WID_];
__device__ float  g_convWt[RED_*KC_];
__device__ float  g_xp[ROWS_*RED_];
__device__ float  g_co[ROWS_*RED_];       // exact (fixup)
__device__ float2 g_co2[ROWS_*RED_];      // {hi, lo}
__device__ float  g_wsum[B_*WID_];

// ---------------- threefry2x32 (JAX-compatible, partitionable mode) ----------------
__host__ __device__ constexpr unsigned rotl32c(unsigned v, int s) {
    return (v << s) | (v >> (32 - s));
}
struct K2 { unsigned a, b; };
constexpr K2 tf_const(unsigned k0, unsigned k1, unsigned x0, unsigned x1) {
    unsigned ks2 = k0 ^ k1 ^ 0x1BD11BDAu;
    unsigned ks[3] = {k0, k1, ks2};
    x0 += k0; x1 += k1;
    const int R[20] = {13,15,26,6, 17,29,16,24, 13,15,26,6, 17,29,16,24, 13,15,26,6};
    for (int g = 0; g < 5; ++g) {
        for (int j = 0; j < 4; ++j) { x0 += x1; x1 = rotl32c(x1, R[g*4+j]); x1 ^= x0; }
        x0 += ks[(g+1)%3];
        x1 += ks[(g+2)%3] + (unsigned)(g+1);
    }
    return K2{x0, x1};
}
constexpr K2 SUBKEY = tf_const(0u, 42u, 0u, 1u);
constexpr unsigned SK0 = SUBKEY.a;
constexpr unsigned SK1 = SUBKEY.b;

__device__ __forceinline__ uint2 tf2x32(unsigned k0, unsigned k1, unsigned x0, unsigned x1) {
    unsigned ks2 = k0 ^ k1 ^ 0x1BD11BDAu;
    x0 += k0; x1 += k1;
#define TFR(r) { x0 += x1; x1 = __funnelshift_l(x1, x1, (r)); x1 ^= x0; }
    TFR(13) TFR(15) TFR(26) TFR(6)   x0 += k1;  x1 += ks2 + 1u;
    TFR(17) TFR(29) TFR(16) TFR(24)  x0 += ks2; x1 += k0  + 2u;
    TFR(13) TFR(15) TFR(26) TFR(6)   x0 += k0;  x1 += k1  + 3u;
    TFR(17) TFR(29) TFR(16) TFR(24)  x0 += k1;  x1 += ks2 + 4u;
    TFR(13) TFR(15) TFR(26) TFR(6)   x0 += ks2; x1 += k0  + 5u;
#undef TFR
    return make_uint2(x0, x1);
}
__device__ __forceinline__ unsigned rbits32(unsigned idx) {
    uint2 r = tf2x32(SK0, SK1, 0u, idx);
    return r.x ^ r.y;
}

// ---------------- packed f32x2 helpers ----------------
__device__ __forceinline__ void ffma2(unsigned long long& acc,
                                      unsigned long long a,
                                      unsigned long long b) {
    asm("fma.rn.f32x2 %0, %1, %2, %0;" : "+l"(acc) : "l"(a), "l"(b));
}
__device__ __forceinline__ unsigned long long dup_f32x2(float x) {
    unsigned long long d;
    asm("mov.b64 %0, {%1, %1};" : "=l"(d) : "f"(x));
    return d;
}
__device__ __forceinline__ float2 unpack_f32x2(unsigned long long v) {
    float lo, hi;
    asm("mov.b64 {%0, %1}, %2;" : "=f"(lo), "=f"(hi) : "l"(v));
    return make_float2(lo, hi);
}

// ---------------- tf32 helpers ----------------
__device__ __forceinline__ float tf32_hi(float x) {
    uint32_t u; asm("cvt.rna.tf32.f32 %0, %1;" : "=r"(u) : "f"(x));
    return __uint_as_float(u);
}
#define MMA_TF32(c, a, b) \
    asm volatile("mma.sync.aligned.m16n8k8.row.col.f32.tf32.tf32.f32 " \
        "{%0,%1,%2,%3}, {%4,%5,%6,%7}, {%8,%9}, {%0,%1,%2,%3};" \
        : "+f"((c)[0]), "+f"((c)[1]), "+f"((c)[2]), "+f"((c)[3]) \
        : "r"(__float_as_uint((a)[0])), "r"(__float_as_uint((a)[1])), \
          "r"(__float_as_uint((a)[2])), "r"(__float_as_uint((a)[3])), \
          "r"(__float_as_uint((b)[0])), "r"(__float_as_uint((b)[1])))

__device__ __forceinline__ uint32_t smem_u32(const void* p) {
    uint32_t a;
    asm("{ .reg .u64 t; cvta.to.shared.u64 t, %1; cvt.u32.u64 %0, t; }" : "=r"(a) : "l"(p));
    return a;
}
#define CP_ASYNC16(s, g) \
    asm volatile("cp.async.cg.shared.global [%0], [%1], 16;" :: "r"(s), "l"(g))
#define CP_COMMIT()  asm volatile("cp.async.commit_group;")
#define CP_WAIT0()   asm volatile("cp.async.wait_group 0;")

// ---------------- small kernels ----------------
__global__ void init_k() {
    if (threadIdx.x < 4) g_absmax[threadIdx.x] = 0u;
    if (threadIdx.x == 0) g_count = 0u;
}
__global__ void absmax_k(const float* __restrict__ W, int n, int which) {
    float m = 0.0f;
    for (int i = blockIdx.x*blockDim.x + threadIdx.x; i < n; i += gridDim.x*blockDim.x)
        m = fmaxf(m, fabsf(W[i]));
    #pragma unroll
    for (int o = 16; o; o >>= 1) m = fmaxf(m, __shfl_xor_sync(0xffffffffu, m, o));
    if ((threadIdx.x & 31) == 0) atomicMax(&g_absmax[which], __float_as_uint(m));
}
__global__ void quant_k(const float* __restrict__ W, float* __restrict__ Q, int n, int which) {
    float scale = fmaxf(__fdiv_rn(__uint_as_float(g_absmax[which]), 7.0f), 1e-8f);
    int i = blockIdx.x*blockDim.x + threadIdx.x;
    if (i < n) Q[i] = __fmul_rn(rintf(__fdiv_rn(W[i], scale)), scale);
}
// quant: store exact qfc1 AND integer k (tf32-exact)
__global__ void quant_int_k(const float* __restrict__ W, float* __restrict__ Q,
                            float* __restrict__ Qk, int n, int which) {
    float scale = fmaxf(__fdiv_rn(__uint_as_float(g_absmax[which]), 7.0f), 1e-8f);
    int i = blockIdx.x*blockDim.x + threadIdx.x;
    if (i < n) {
        float k = rintf(__fdiv_rn(W[i], scale));
        Q[i]  = __fmul_rn(k, scale);
        Qk[i] = k;
    }
}
__global__ void convT_k(const float* __restrict__ convW) {
    int idx = blockIdx.x*blockDim.x + threadIdx.x;
    if (idx >= RED_*KC_) return;
    int o = idx / KC_, rem = idx % KC_;
    int k = rem >> 8, i = rem & 255;
    g_convWt[idx] = convW[o*KC_ + i*5 + k];
}

// ---------------- FFMA2 double-buffered SGEMM 128x128x16 (exact fp32) ----------------
template<int CONV>
__device__ __forceinline__ float4 ldA(const float* __restrict__ A, int K, int row, int c) {
    if (CONV) {
        int tap = c >> 8, chn = c & 255;
        int b = row / T_, t = row - b*T_;
        int ts = t + tap - 2;
        if (ts < 0 || ts >= T_) return make_float4(0,0,0,0);
        return *reinterpret_cast<const float4*>(A + (size_t)(b*T_ + ts)*RED_ + chn);
    } else {
        if (c >= K) return make_float4(0,0,0,0);
        return *reinterpret_cast<const float4*>(A + (size_t)row*K + c);
    }
}

template<int CONV, int SPLIT>
__global__ __launch_bounds__(256, 2)
void sgemm_k(const float* __restrict__ A, const float* __restrict__ B,
             const float* __restrict__ bias, float* __restrict__ C,
             float2* __restrict__ Cs, int K, int N)
{
    __shared__ float sA[2][16][128];
    __shared__ float sB[2][16][128];

    const int tid  = threadIdx.x;
    const int lane = tid & 31;
    const int wid  = tid >> 5;
    const int lr   = lane >> 2;
    const int lc   = lane & 3;
    const int wm   = (wid & 1) * 64;
    const int wn   = (wid >> 1) * 32;
    const int bm0  = blockIdx.y * 128, bn0 = blockIdx.x * 128;

    unsigned long long acc2[2][2][4][2];
    #pragma unroll
    for (int im = 0; im < 2; ++im)
        #pragma unroll
        for (int in = 0; in < 2; ++in)
            #pragma unroll
            for (int i = 0; i < 4; ++i) {
                acc2[im][in][i][0] = 0ull;
                acc2[im][in][i][1] = 0ull;
            }

    const int nch = (K + 15) >> 4;
    float4 va[2], vb[2];

    {
        #pragma unroll
        for (int i = 0; i < 2; ++i) {
            int q = tid + 256*i;
            int row = q >> 2, c = (q & 3) * 4;
            va[i] = ldA<CONV>(A, K, bm0 + row, c);
            vb[i] = (c < K) ? *reinterpret_cast<const float4*>(B + (size_t)(bn0+row)*K + c)
                            : make_float4(0,0,0,0);
        }
        #pragma unroll
        for (int i = 0; i < 2; ++i) {
            int q = tid + 256*i;
            int row = q >> 2, c4 = (q & 3) * 4;
            sA[0][c4+0][row] = va[i].x; sA[0][c4+1][row] = va[i].y;
            sA[0][c4+2][row] = va[i].z; sA[0][c4+3][row] = va[i].w;
            sB[0][c4+0][row] = vb[i].x; sB[0][c4+1][row] = vb[i].y;
            sB[0][c4+2][row] = vb[i].z; sB[0][c4+3][row] = vb[i].w;
        }
        __syncthreads();
    }

    int p = 0;
    for (int ch = 0; ch < nch; ++ch) {
        const bool more = (ch + 1 < nch);
        if (more) {
            int k0 = (ch + 1) * 16;
            #pragma unroll
            for (int i = 0; i < 2; ++i) {
                int q = tid + 256*i;
                int row = q >> 2, c = k0 + (q & 3) * 4;
                va[i] = ldA<CONV>(A, K, bm0 + row, c);
                vb[i] = (c < K) ? *reinterpret_cast<const float4*>(B + (size_t)(bn0+row)*K + c)
                                : make_float4(0,0,0,0);
            }
        }
        #pragma unroll
        for (int kk = 0; kk < 16; ++kk) {
            float4 a0 = *reinterpret_cast<const float4*>(&sA[p][kk][wm + lr*4]);
            float4 a1 = *reinterpret_cast<const float4*>(&sA[p][kk][wm + 32 + lr*4]);
            ulonglong2 b0 = *reinterpret_cast<const ulonglong2*>(&sB[p][kk][wn + lc*4]);
            ulonglong2 b1 = *reinterpret_cast<const ulonglong2*>(&sB[p][kk][wn + 16 + lc*4]);
            unsigned long long bp[2][2] = { { b0.x, b0.y }, { b1.x, b1.y } };
            const float av[2][4] = { { a0.x, a0.y, a0.z, a0.w },
                                     { a1.x, a1.y, a1.z, a1.w } };
            #pragma unroll
            for (int im = 0; im < 2; ++im)
                #pragma unroll
                for (int i = 0; i < 4; ++i) {
                    unsigned long long ad = dup_f32x2(av[im][i]);
                    #pragma unroll
                    for (int in = 0; in < 2; ++in) {
                        ffma2(acc2[im][in][i][0], ad, bp[in][0]);
                        ffma2(acc2[im][in][i][1], ad, bp[in][1]);
                    }
                }
        }
        if (more) {
            int q2 = p ^ 1;
            #pragma unroll
            for (int i = 0; i < 2; ++i) {
                int q = tid + 256*i;
                int row = q >> 2, c4 = (q & 3) * 4;
                sA[q2][c4+0][row] = va[i].x; sA[q2][c4+1][row] = va[i].y;
                sA[q2][c4+2][row] = va[i].z; sA[q2][c4+3][row] = va[i].w;
                sB[q2][c4+0][row] = vb[i].x; sB[q2][c4+1][row] = vb[i].y;
                sB[q2][c4+2][row] = vb[i].z; sB[q2][c4+3][row] = vb[i].w;
            }
            __syncthreads();
            p = q2;
        }
    }

    #pragma unroll
    for (int im = 0; im < 2; ++im)
        #pragma unroll
        for (int i = 0; i < 4; ++i) {
            int row = bm0 + wm + im*32 + lr*4 + i;
            #pragma unroll
            for (int in = 0; in < 2; ++in) {
                int col = bn0 + wn + in*16 + lc*4;
                float2 p01 = unpack_f32x2(acc2[im][in][i][0]);
                float2 p23 = unpack_f32x2(acc2[im][in][i][1]);
                float4 v;
                v.x = fmaxf(p01.x + __ldg(bias + col + 0), 0.0f);
                v.y = fmaxf(p01.y + __ldg(bias + col + 1), 0.0f);
                v.z = fmaxf(p23.x + __ldg(bias + col + 2), 0.0f);
                v.w = fmaxf(p23.y + __ldg(bias + col + 3), 0.0f);
                *reinterpret_cast<float4*>(C + (size_t)row*N + col) = v;
                if (SPLIT) {
                    const float* vf = &v.x;
                    float4 s01, s23;
                    float* sp01 = &s01.x; float* sp23 = &s23.x;
                    #pragma unroll
                    for (int q = 0; q < 2; ++q) {
                        float hi = tf32_hi(vf[q]);
                        sp01[q*2+0] = hi; sp01[q*2+1] = tf32_hi(vf[q] - hi);
                    }
                    #pragma unroll
                    for (int q = 2; q < 4; ++q) {
                        float hi = tf32_hi(vf[q]);
                        sp23[(q-2)*2+0] = hi; sp23[(q-2)*2+1] = tf32_hi(vf[q] - hi);
                    }
                    *reinterpret_cast<float4*>(Cs + (size_t)row*N + col)     = s01;
                    *reinterpret_cast<float4*>(Cs + (size_t)row*N + col + 2) = s23;
                }
            }
        }
}

// ---------------- GEMM2: 2-pass tf32 (B = int4 levels, scale factored out) -----------
// BM=128, BN=64, BK=16, 8 warps (4x2), warp tile 32x32. cp.async double-buffered.
#define AST 20                          // padded k-stride (float2 for A, float for B)
#define ASZ (128*AST)                   // A buffer, float2
#define BSZ (64*AST)                    // B buffer, float
#define G2_SMEM (2*ASZ*8 + 2*BSZ*4)     // 46080 B

__device__ __forceinline__ void g2_issue(const float2* __restrict__ co2,
                                         const float* __restrict__ qk,
                                         uint32_t sAa, uint32_t sBa,
                                         int bm0, int bn0, int k0, int tid) {
    #pragma unroll
    for (int i = 0; i < 4; ++i) {
        int cid = tid + 256*i;
        int row = cid >> 3, kp = (cid & 7) * 2;
        const float2* g = co2 + (size_t)(bm0+row)*RED_ + k0 + kp;
        CP_ASYNC16(sAa + (uint32_t)((row*AST + kp) * 8), g);
    }
    {
        int row = tid >> 2, kq = (tid & 3) * 4;
        const float* g = qk + (size_t)(bn0+row)*RED_ + k0 + kq;
        CP_ASYNC16(sBa + (uint32_t)((row*AST + kq) * 4), g);
    }
    CP_COMMIT();
}

__global__ __launch_bounds__(256, 3)
void g2tf_k(const float2* __restrict__ co2, const float* __restrict__ qk,
            const float* __restrict__ bias,
            const float* __restrict__ latent, const float* __restrict__ gainp,
            float* __restrict__ drv, float* __restrict__ spk)
{
    extern __shared__ float2 smf2[];
    const uint32_t smem_base = smem_u32(smf2);
    float* smB = reinterpret_cast<float*>(smf2 + 2*ASZ);

    const int tid  = threadIdx.x;
    const int lane = tid & 31;
    const int wid  = tid >> 5;
    const int wm   = (wid & 3) * 32;
    const int wn   = (wid >> 2) * 32;
    const int bm0  = blockIdx.y * 128, bn0 = blockIdx.x * 64;

    float acc[2][4][4];
    #pragma unroll
    for (int mi = 0; mi < 2; ++mi)
        #pragma unroll
        for (int ni = 0; ni < 4; ++ni)
            #pragma unroll
            for (int q = 0; q < 4; ++q) acc[mi][ni][q] = 0.0f;

    g2_issue(co2, qk, smem_base, smem_base + 2*ASZ*8, bm0, bn0, 0, tid);

    #pragma unroll 1
    for (int ch = 0; ch < 16; ++ch) {
        CP_WAIT0();
        __syncthreads();
        const int p = ch & 1;
        if (ch + 1 < 16) {
            const int q2 = p ^ 1;
            g2_issue(co2, qk, smem_base + q2*ASZ*8,
                     smem_base + 2*ASZ*8 + q2*BSZ*4, bm0, bn0, (ch+1)*16, tid);
        }
        const float2* A2 = smf2 + p*ASZ;
        const float*  B2 = smB + p*BSZ;
        #pragma unroll
        for (int ksl = 0; ksl < 2; ++ksl) {
            const int bc = ksl*8 + (lane & 3);
            float2 afr[2][4];
            #pragma unroll
            for (int mi = 0; mi < 2; ++mi) {
                int r = wm + (lane >> 2) + mi*16;
                afr[mi][0] = A2[r*AST + bc];
                afr[mi][1] = A2[(r+8)*AST + bc];
                afr[mi][2] = A2[r*AST + bc + 4];
                afr[mi][3] = A2[(r+8)*AST + bc + 4];
            }
            float bfr[4][2];
            #pragma unroll
            for (int ni = 0; ni < 4; ++ni) {
                int n = wn + ni*8 + (lane >> 2);
                bfr[ni][0] = B2[n*AST + bc];
                bfr[ni][1] = B2[n*AST + bc + 4];
            }
            #pragma unroll
            for (int mi = 0; mi < 2; ++mi) {
                float ah[4] = { afr[mi][0].x, afr[mi][1].x, afr[mi][2].x, afr[mi][3].x };
                float al[4] = { afr[mi][0].y, afr[mi][1].y, afr[mi][2].y, afr[mi][3].y };
                #pragma unroll
                for (int ni = 0; ni < 4; ++ni) {
                    MMA_TF32(acc[mi][ni], ah, bfr[ni]);
                    MMA_TF32(acc[mi][ni], al, bfr[ni]);
                }
            }
        }
    }

    // epilogue: apply factored scale, fast-math drive, spike + borderline flag
    const int r0 = bm0 + wm + (lane >> 2);
    const int c0 = bn0 + wn + (lane & 3)*2;
    const float gabs = fabsf(gainp[0]);
    const float scaleB = fmaxf(__fdiv_rn(__uint_as_float(g_absmax[1]), 7.0f), 1e-8f);

    #pragma unroll
    for (int mi = 0; mi < 2; ++mi)
        #pragma unroll
        for (int ni = 0; ni < 4; ++ni) {
            int col = c0 + ni*8;
            float b0 = __ldg(bias + col), b1 = __ldg(bias + col + 1);
            #pragma unroll
            for (int h = 0; h < 2; ++h) {
                int row = r0 + mi*16 + h*8;
                float lat = __ldg(latent + (row % T_));
                float2 dv, sv;
                #pragma unroll
                for (int q = 0; q < 2; ++q) {
                    float pre = fmaf(acc[mi][ni][h*2+q], scaleB, q ? b1 : b0);
                    float e   = __expf(-fabsf(pre));
                    float sp  = fmaxf(pre, 0.0f) + __logf(1.0f + e);
                    float d   = (sp * lat) * gabs;
                    unsigned idx = (unsigned)row * (unsigned)WID_ + (unsigned)(col + q);
                    unsigned bits = rbits32(idx);
                    float u = __uint_as_float((bits >> 9) | 0x3f800000u) - 1.0f;
                    float spike;
                    if (d >= 10.0f) spike = 1.0f;
                    else {
                        float t = __expf(-d);
                        spike = (u > t) ? 1.0f : 0.0f;
                        if (fabsf(u - t) < MARGIN * t) {
                            unsigned w = atomicAdd(&g_count, 1u);
                            if (w < WCAP) g_worklist[w] = idx;
                        }
                    }
                    if (q) { dv.y = d; sv.y = spike; } else { dv.x = d; sv.x = spike; }
                }
                size_t ob = (size_t)row * WID_ + col;
                *reinterpret_cast<float2*>(drv + ob) = dv;
                *reinterpret_cast<float2*>(spk + ob) = sv;
            }
        }
}

// ---------------- exact fp32 fixup for borderline spikes (reference semantics) --------
__global__ void fixup_k(const float* __restrict__ co, const float* __restrict__ qfc1,
                        const float* __restrict__ bias, const float* __restrict__ latent,
                        const float* __restrict__ gainp, float* __restrict__ spk)
{
    __shared__ float red[4];
    const unsigned n = (g_count < WCAP) ? g_count : WCAP;
    const float gabs = fabsf(gainp[0]);
    const int tid = threadIdx.x;   // 128
    for (unsigned i = blockIdx.x; i < n; i += gridDim.x) {
        unsigned idx = g_worklist[i];
        int row = idx >> 12, col = idx & (WID_-1);
        const float* cr = co + (size_t)row * RED_;
        const float* wr = qfc1 + (size_t)col * RED_;
        float s = cr[tid]*wr[tid] + cr[tid+128]*wr[tid+128];
        #pragma unroll
        for (int o = 16; o; o >>= 1) s += __shfl_xor_sync(0xffffffffu, s, o);
        if ((tid & 31) == 0) red[tid >> 5] = s;
        __syncthreads();
        if (tid == 0) {
            float pre = (red[0]+red[1]) + (red[2]+red[3]) + bias[col];
            float spl = fmaxf(pre, 0.0f) + log1pf(expf(-fabsf(pre)));
            float d   = (spl * latent[row % T_]) * gabs;
            unsigned bits = rbits32(idx);
            float u = __uint_as_float((bits >> 9) | 0x3f800000u) - 1.0f;
            spk[idx] = (d >= 10.0f) ? 1.0f : ((logf(u) > -d) ? 1.0f : 0.0f);
        }
        __syncthreads();
    }
}

// ---------------- decay-weighted temporal reduction ----------------
__global__ void weighted_k(const float* __restrict__ spikes) {
    __shared__ float decay[T_];
    int tid = threadIdx.x;
    if (tid < T_) decay[tid] = expf(-2.0f + (float)tid * (2.0f/99.0f));
    __syncthreads();
    int idx = blockIdx.x * blockDim.x + tid;
    if (idx >= B_*WID_) return;
    int b = idx >> 12, w = idx & (WID_-1);
    const float* sp = spikes + (size_t)b*T_*WID_ + w;
    float s = 0.0f;
    #pragma unroll 4
    for (int t = 0; t < T_; ++t) s += sp[(size_t)t*WID_] * decay[t];
    g_wsum[idx] = s;
}

// ---------------- logits ----------------
__global__ void logits_k(const float* __restrict__ bias, float* __restrict__ out) {
    int bc = blockIdx.x;
    int b = bc / CLS_, c = bc % CLS_;
    const float* wr = g_wsum + (size_t)b*WID_;
    const float* fr = g_qfc2 + (size_t)c*WID_;
    float s = 0.0f;
    for (int i = threadIdx.x; i < WID_; i += 128) s += wr[i]*fr[i];
    #pragma unroll
    for (int o = 16; o; o >>= 1) s += __shfl_xor_sync(0xffffffffu, s, o);
    __shared__ float red[4];
    if ((threadIdx.x & 31) == 0) red[threadIdx.x >> 5] = s;
    __syncthreads();
    if (threadIdx.x == 0) out[bc] = (red[0]+red[1]+red[2]+red[3]) + bias[c];
}

// ---------------- launcher ----------------
extern "C" void kernel_launch(void* const* d_in, const int* in_sizes, int n_in,
                              void* d_out, int out_size) {
    (void)in_sizes; (void)n_in; (void)out_size;
    const float* x        = (const float*)d_in[0];
    const float* latent   = (const float*)d_in[1];
    const float* spatialW = (const float*)d_in[2];
    const float* spatialB = (const float*)d_in[3];
    const float* convW    = (const float*)d_in[4];
    const float* convB    = (const float*)d_in[5];
    const float* fc1W     = (const float*)d_in[6];
    const float* fc1B     = (const float*)d_in[7];
    const float* fc2W     = (const float*)d_in[8];
    const float* fc2B     = (const float*)d_in[9];
    const float* gain     = (const float*)d_in[10];

    float* out        = (float*)d_out;
    float* out_logits = out;
    float* out_spk    = out + (CLS_*B_);
    float* out_drv    = out + (CLS_*B_) + (size_t)NELEM_;

    float *qsp, *qfc1, *qk, *qfc2, *cwt, *xp, *co;
    float2 *co2;
    cudaGetSymbolAddress((void**)&qsp,  g_qsp);
    cudaGetSymbolAddress((void**)&qfc1, g_qfc1);
    cudaGetSymbolAddress((void**)&qk,   g_qk);
    cudaGetSymbolAddress((void**)&qfc2, g_qfc2);
    cudaGetSymbolAddress((void**)&cwt,  g_convWt);
    cudaGetSymbolAddress((void**)&xp,   g_xp);
    cudaGetSymbolAddress((void**)&co,   g_co);
    cudaGetSymbolAddress((void**)&co2,  g_co2);

    static bool attr_set = false;
    if (!attr_set) {
        cudaFuncSetAttribute(g2tf_k, cudaFuncAttributeMaxDynamicSharedMemorySize, G2_SMEM);
        attr_set = true;
    }

    init_k<<<1, 32>>>();
    absmax_k<<<128, 256>>>(spatialW, RED_*INF_,  0);
    absmax_k<<<256, 256>>>(fc1W,     WID_*RED_,  1);
    absmax_k<<<128, 256>>>(fc2W,     CLS_*WID_,  2);
    quant_k<<<(RED_*INF_ + 255)/256, 256>>>(spatialW, qsp,  RED_*INF_, 0);
    quant_int_k<<<(WID_*RED_ + 255)/256, 256>>>(fc1W, qfc1, qk, WID_*RED_, 1);
    quant_k<<<(CLS_*WID_ + 255)/256, 256>>>(fc2W,     qfc2, CLS_*WID_, 2);
    convT_k<<<(RED_*KC_ + 255)/256, 256>>>(convW);

    // GEMM1: xp = relu(x @ qsp^T + b)   (exact fp32 FFMA2)
    sgemm_k<0,0><<<dim3(RED_/128, ROWS_/128), 256>>>(x, qsp, spatialB, xp, nullptr, INF_, RED_);
    // conv (fused im2col): co = relu(im2col(xp) @ cwt^T + cb), also emits split co2
    sgemm_k<1,1><<<dim3(RED_/128, ROWS_/128), 256>>>(xp, cwt, convB, co, co2, KC_, RED_);
    // GEMM2 (tf32 2-pass, int4-level B, scale factored) + drive/spike + flags
    g2tf_k<<<dim3(WID_/64, ROWS_/128), 256, G2_SMEM>>>(co2, qk, fc1B,
                                                       latent, gain, out_drv, out_spk);
    // exact recompute of borderline spikes
    fixup_k<<<1024, 128>>>(co, qfc1, fc1B, latent, gain, out_spk);
    weighted_k<<<(B_*WID_ + 255)/256, 256>>>(out_spk);
    logits_k<<<B_*CLS_, 128>>>(fc2B, out_logits);
}

// round 11
// speedup vs baseline: 1.6429x; 1.1208x over previous
#include <cuda_runtime.h>
#include <cstdint>

// ---------------- problem dims ----------------
#define B_    64
#define T_    100
#define INF_  700
#define RED_  256
#define WID_  4096
#define CLS_  20
#define ROWS_ (B_*T_)          // 6400
#define KC_   1280             // conv im2col K (256*5)
#define NELEM_ (ROWS_*WID_)    // 26214400
#define WCAP  (1u<<22)
#define MARGIN 2.5e-3f

#define N0_ (RED_*INF_)        // 179200
#define N1_ (WID_*RED_)        // 1048576
#define N2_ (CLS_*WID_)        // 81920
#define N3_ (RED_*KC_)         // 327680
#define NPREP_ (N0_+N1_+N2_+N3_)   // 1637376 = 6396*256

// ---------------- scratch (static device globals; no alloc allowed) ----------------
__device__ unsigned g_absmax[4];
__device__ unsigned g_count;
__device__ unsigned g_worklist[WCAP];
__device__ float  g_qsp[RED_*INF_];
__device__ float  g_qfc1[WID_*RED_];      // exact scale*k (fixup)
__device__ float  g_qk[WID_*RED_];        // integer k as float (tf32-exact)
__device__ float  g_qfc2[CLS_*WID_];
__device__ float  g_convWt[RED_*KC_];
__device__ float  g_xp[ROWS_*RED_];
__device__ float  g_co[ROWS_*RED_];       // exact (fixup)
__device__ float  g_coh[ROWS_*RED_];      // tf32 hi of co
__device__ float  g_wsum[B_*WID_];

// ---------------- threefry2x32 (JAX-compatible, partitionable mode) ----------------
__host__ __device__ constexpr unsigned rotl32c(unsigned v, int s) {
    return (v << s) | (v >> (32 - s));
}
struct K2 { unsigned a, b; };
constexpr K2 tf_const(unsigned k0, unsigned k1, unsigned x0, unsigned x1) {
    unsigned ks2 = k0 ^ k1 ^ 0x1BD11BDAu;
    unsigned ks[3] = {k0, k1, ks2};
    x0 += k0; x1 += k1;
    const int R[20] = {13,15,26,6, 17,29,16,24, 13,15,26,6, 17,29,16,24, 13,15,26,6};
    for (int g = 0; g < 5; ++g) {
        for (int j = 0; j < 4; ++j) { x0 += x1; x1 = rotl32c(x1, R[g*4+j]); x1 ^= x0; }
        x0 += ks[(g+1)%3];
        x1 += ks[(g+2)%3] + (unsigned)(g+1);
    }
    return K2{x0, x1};
}
constexpr K2 SUBKEY = tf_const(0u, 42u, 0u, 1u);
constexpr unsigned SK0 = SUBKEY.a;
constexpr unsigned SK1 = SUBKEY.b;

__device__ __forceinline__ uint2 tf2x32(unsigned k0, unsigned k1, unsigned x0, unsigned x1) {
    unsigned ks2 = k0 ^ k1 ^ 0x1BD11BDAu;
    x0 += k0; x1 += k1;
#define TFR(r) { x0 += x1; x1 = __funnelshift_l(x1, x1, (r)); x1 ^= x0; }
    TFR(13) TFR(15) TFR(26) TFR(6)   x0 += k1;  x1 += ks2 + 1u;
    TFR(17) TFR(29) TFR(16) TFR(24)  x0 += ks2; x1 += k0  + 2u;
    TFR(13) TFR(15) TFR(26) TFR(6)   x0 += k0;  x1 += k1  + 3u;
    TFR(17) TFR(29) TFR(16) TFR(24)  x0 += k1;  x1 += ks2 + 4u;
    TFR(13) TFR(15) TFR(26) TFR(6)   x0 += ks2; x1 += k0  + 5u;
#undef TFR
    return make_uint2(x0, x1);
}
__device__ __forceinline__ unsigned rbits32(unsigned idx) {
    uint2 r = tf2x32(SK0, SK1, 0u, idx);
    return r.x ^ r.y;
}

// ---------------- packed f32x2 helpers ----------------
__device__ __forceinline__ void ffma2(unsigned long long& acc,
                                      unsigned long long a,
                                      unsigned long long b) {
    asm("fma.rn.f32x2 %0, %1, %2, %0;" : "+l"(acc) : "l"(a), "l"(b));
}
__device__ __forceinline__ unsigned long long dup_f32x2(float x) {
    unsigned long long d;
    asm("mov.b64 %0, {%1, %1};" : "=l"(d) : "f"(x));
    return d;
}
__device__ __forceinline__ float2 unpack_f32x2(unsigned long long v) {
    float lo, hi;
    asm("mov.b64 {%0, %1}, %2;" : "=f"(lo), "=f"(hi) : "l"(v));
    return make_float2(lo, hi);
}

// ---------------- tf32 helpers ----------------
__device__ __forceinline__ float tf32_hi(float x) {
    uint32_t u; asm("cvt.rna.tf32.f32 %0, %1;" : "=r"(u) : "f"(x));
    return __uint_as_float(u);
}
#define MMA_TF32(c, a, b) \
    asm volatile("mma.sync.aligned.m16n8k8.row.col.f32.tf32.tf32.f32 " \
        "{%0,%1,%2,%3}, {%4,%5,%6,%7}, {%8,%9}, {%0,%1,%2,%3};" \
        : "+f"((c)[0]), "+f"((c)[1]), "+f"((c)[2]), "+f"((c)[3]) \
        : "r"(__float_as_uint((a)[0])), "r"(__float_as_uint((a)[1])), \
          "r"(__float_as_uint((a)[2])), "r"(__float_as_uint((a)[3])), \
          "r"(__float_as_uint((b)[0])), "r"(__float_as_uint((b)[1])))

__device__ __forceinline__ uint32_t smem_u32(const void* p) {
    uint32_t a;
    asm("{ .reg .u64 t; cvta.to.shared.u64 t, %1; cvt.u32.u64 %0, t; }" : "=r"(a) : "l"(p));
    return a;
}
#define CP_ASYNC16(s, g) \
    asm volatile("cp.async.cg.shared.global [%0], [%1], 16;" :: "r"(s), "l"(g))
#define CP_COMMIT()  asm volatile("cp.async.commit_group;")
#define CP_WAIT0()   asm volatile("cp.async.wait_group 0;")

// ---------------- prep kernels ----------------
__global__ void init_k() {
    if (threadIdx.x < 4) g_absmax[threadIdx.x] = 0u;
    if (threadIdx.x == 0) g_count = 0u;
}
// merged absmax over 3 tensors: blocks [0,64) W0, [64,320) W1, [320,384) W2
__global__ void absmax3_k(const float* __restrict__ W0, const float* __restrict__ W1,
                          const float* __restrict__ W2) {
    const float* W; int n, which, b0, nb;
    if (blockIdx.x < 64)        { W = W0; n = N0_; which = 0; b0 = 0;   nb = 64;  }
    else if (blockIdx.x < 320)  { W = W1; n = N1_; which = 1; b0 = 64;  nb = 256; }
    else                        { W = W2; n = N2_; which = 2; b0 = 320; nb = 64;  }
    float m = 0.0f;
    for (int i = (int)(blockIdx.x - b0)*blockDim.x + threadIdx.x; i < n; i += nb*blockDim.x)
        m = fmaxf(m, fabsf(W[i]));
    #pragma unroll
    for (int o = 16; o; o >>= 1) m = fmaxf(m, __shfl_xor_sync(0xffffffffu, m, o));
    if ((threadIdx.x & 31) == 0) atomicMax(&g_absmax[which], __float_as_uint(m));
}
// merged quantization + conv transpose
__global__ void prep_k(const float* __restrict__ spW, const float* __restrict__ fc1W,
                       const float* __restrict__ fc2W, const float* __restrict__ convW) {
    int i = blockIdx.x*blockDim.x + threadIdx.x;
    if (i < N0_) {
        float scale = fmaxf(__fdiv_rn(__uint_as_float(g_absmax[0]), 7.0f), 1e-8f);
        g_qsp[i] = __fmul_rn(rintf(__fdiv_rn(spW[i], scale)), scale);
    } else if (i < N0_ + N1_) {
        int j = i - N0_;
        float scale = fmaxf(__fdiv_rn(__uint_as_float(g_absmax[1]), 7.0f), 1e-8f);
        float k = rintf(__fdiv_rn(fc1W[j], scale));
        g_qfc1[j] = __fmul_rn(k, scale);
        g_qk[j]   = k;
    } else if (i < N0_ + N1_ + N2_) {
        int j = i - N0_ - N1_;
        float scale = fmaxf(__fdiv_rn(__uint_as_float(g_absmax[2]), 7.0f), 1e-8f);
        g_qfc2[j] = __fmul_rn(rintf(__fdiv_rn(fc2W[j], scale)), scale);
    } else {
        int j = i - N0_ - N1_ - N2_;
        int o = j / KC_, rem = j % KC_;
        int k = rem >> 8, c = rem & 255;
        g_convWt[j] = convW[o*KC_ + c*5 + k];
    }
}

// ---------------- FFMA2 double-buffered SGEMM 128x128x16 (exact fp32) ----------------
template<int CONV>
__device__ __forceinline__ float4 ldA(const float* __restrict__ A, int K, int row, int c) {
    if (CONV) {
        int tap = c >> 8, chn = c & 255;
        int b = row / T_, t = row - b*T_;
        int ts = t + tap - 2;
        if (ts < 0 || ts >= T_) return make_float4(0,0,0,0);
        return *reinterpret_cast<const float4*>(A + (size_t)(b*T_ + ts)*RED_ + chn);
    } else {
        if (c >= K) return make_float4(0,0,0,0);
        return *reinterpret_cast<const float4*>(A + (size_t)row*K + c);
    }
}

template<int CONV, int SPLIT>
__global__ __launch_bounds__(256, 2)
void sgemm_k(const float* __restrict__ A, const float* __restrict__ B,
             const float* __restrict__ bias, float* __restrict__ C,
             float* __restrict__ Ch, int K, int N)
{
    __shared__ float sA[2][16][128];
    __shared__ float sB[2][16][128];

    const int tid  = threadIdx.x;
    const int lane = tid & 31;
    const int wid  = tid >> 5;
    const int lr   = lane >> 2;
    const int lc   = lane & 3;
    const int wm   = (wid & 1) * 64;
    const int wn   = (wid >> 1) * 32;
    const int bm0  = blockIdx.y * 128, bn0 = blockIdx.x * 128;

    unsigned long long acc2[2][2][4][2];
    #pragma unroll
    for (int im = 0; im < 2; ++im)
        #pragma unroll
        for (int in = 0; in < 2; ++in)
            #pragma unroll
            for (int i = 0; i < 4; ++i) {
                acc2[im][in][i][0] = 0ull;
                acc2[im][in][i][1] = 0ull;
            }

    const int nch = (K + 15) >> 4;
    float4 va[2], vb[2];

    {
        #pragma unroll
        for (int i = 0; i < 2; ++i) {
            int q = tid + 256*i;
            int row = q >> 2, c = (q & 3) * 4;
            va[i] = ldA<CONV>(A, K, bm0 + row, c);
            vb[i] = (c < K) ? *reinterpret_cast<const float4*>(B + (size_t)(bn0+row)*K + c)
                            : make_float4(0,0,0,0);
        }
        #pragma unroll
        for (int i = 0; i < 2; ++i) {
            int q = tid + 256*i;
            int row = q >> 2, c4 = (q & 3) * 4;
            sA[0][c4+0][row] = va[i].x; sA[0][c4+1][row] = va[i].y;
            sA[0][c4+2][row] = va[i].z; sA[0][c4+3][row] = va[i].w;
            sB[0][c4+0][row] = vb[i].x; sB[0][c4+1][row] = vb[i].y;
            sB[0][c4+2][row] = vb[i].z; sB[0][c4+3][row] = vb[i].w;
        }
        __syncthreads();
    }

    int p = 0;
    for (int ch = 0; ch < nch; ++ch) {
        const bool more = (ch + 1 < nch);
        if (more) {
            int k0 = (ch + 1) * 16;
            #pragma unroll
            for (int i = 0; i < 2; ++i) {
                int q = tid + 256*i;
                int row = q >> 2, c = k0 + (q & 3) * 4;
                va[i] = ldA<CONV>(A, K, bm0 + row, c);
                vb[i] = (c < K) ? *reinterpret_cast<const float4*>(B + (size_t)(bn0+row)*K + c)
                                : make_float4(0,0,0,0);
            }
        }
        #pragma unroll
        for (int kk = 0; kk < 16; ++kk) {
            float4 a0 = *reinterpret_cast<const float4*>(&sA[p][kk][wm + lr*4]);
            float4 a1 = *reinterpret_cast<const float4*>(&sA[p][kk][wm + 32 + lr*4]);
            ulonglong2 b0 = *reinterpret_cast<const ulonglong2*>(&sB[p][kk][wn + lc*4]);
            ulonglong2 b1 = *reinterpret_cast<const ulonglong2*>(&sB[p][kk][wn + 16 + lc*4]);
            unsigned long long bp[2][2] = { { b0.x, b0.y }, { b1.x, b1.y } };
            const float av[2][4] = { { a0.x, a0.y, a0.z, a0.w },
                                     { a1.x, a1.y, a1.z, a1.w } };
            #pragma unroll
            for (int im = 0; im < 2; ++im)
                #pragma unroll
                for (int i = 0; i < 4; ++i) {
                    unsigned long long ad = dup_f32x2(av[im][i]);
                    #pragma unroll
                    for (int in = 0; in < 2; ++in) {
                        ffma2(acc2[im][in][i][0], ad, bp[in][0]);
                        ffma2(acc2[im][in][i][1], ad, bp[in][1]);
                    }
                }
        }
        if (more) {
            int q2 = p ^ 1;
            #pragma unroll
            for (int i = 0; i < 2; ++i) {
                int q = tid + 256*i;
                int row = q >> 2, c4 = (q & 3) * 4;
                sA[q2][c4+0][row] = va[i].x; sA[q2][c4+1][row] = va[i].y;
                sA[q2][c4+2][row] = va[i].z; sA[q2][c4+3][row] = va[i].w;
                sB[q2][c4+0][row] = vb[i].x; sB[q2][c4+1][row] = vb[i].y;
                sB[q2][c4+2][row] = vb[i].z; sB[q2][c4+3][row] = vb[i].w;
            }
            __syncthreads();
            p = q2;
        }
    }

    #pragma unroll
    for (int im = 0; im < 2; ++im)
        #pragma unroll
        for (int i = 0; i < 4; ++i) {
            int row = bm0 + wm + im*32 + lr*4 + i;
            #pragma unroll
            for (int in = 0; in < 2; ++in) {
                int col = bn0 + wn + in*16 + lc*4;
                float2 p01 = unpack_f32x2(acc2[im][in][i][0]);
                float2 p23 = unpack_f32x2(acc2[im][in][i][1]);
                float4 v;
                v.x = fmaxf(p01.x + __ldg(bias + col + 0), 0.0f);
                v.y = fmaxf(p01.y + __ldg(bias + col + 1), 0.0f);
                v.z = fmaxf(p23.x + __ldg(bias + col + 2), 0.0f);
                v.w = fmaxf(p23.y + __ldg(bias + col + 3), 0.0f);
                *reinterpret_cast<float4*>(C + (size_t)row*N + col) = v;
                if (SPLIT) {
                    float4 hv;
                    hv.x = tf32_hi(v.x); hv.y = tf32_hi(v.y);
                    hv.z = tf32_hi(v.z); hv.w = tf32_hi(v.w);
                    *reinterpret_cast<float4*>(Ch + (size_t)row*N + col) = hv;
                }
            }
        }
}

// ---------------- GEMM2: 1-pass tf32 (A = tf32(co), B = int4 levels) ------------------
// BM=128, BN=64, BK=16, 8 warps (4x2), warp tile 32x32. cp.async double-buffered.
#define AST 20                          // padded k-stride (floats)
#define ASZ (128*AST)                   // A buffer floats
#define BSZ (64*AST)                    // B buffer floats
#define G2_SMEM ((2*ASZ + 2*BSZ)*4)     // 30720 B

__device__ __forceinline__ void g2_issue(const float* __restrict__ coh,
                                         const float* __restrict__ qk,
                                         uint32_t sAa, uint32_t sBa,
                                         int bm0, int bn0, int k0, int tid) {
    #pragma unroll
    for (int i = 0; i < 2; ++i) {
        int cid = tid + 256*i;
        int row = cid >> 2, kq = (cid & 3) * 4;
        const float* g = coh + (size_t)(bm0+row)*RED_ + k0 + kq;
        CP_ASYNC16(sAa + (uint32_t)((row*AST + kq) * 4), g);
    }
    {
        int row = tid >> 2, kq = (tid & 3) * 4;
        const float* g = qk + (size_t)(bn0+row)*RED_ + k0 + kq;
        CP_ASYNC16(sBa + (uint32_t)((row*AST + kq) * 4), g);
    }
    CP_COMMIT();
}

__global__ __launch_bounds__(256, 3)
void g2tf_k(const float* __restrict__ coh, const float* __restrict__ qk,
            const float* __restrict__ bias,
            const float* __restrict__ latent, const float* __restrict__ gainp,
            float* __restrict__ drv, float* __restrict__ spk)
{
    extern __shared__ float smf[];
    const uint32_t smem_base = smem_u32(smf);
    float* smB = smf + 2*ASZ;

    const int tid  = threadIdx.x;
    const int lane = tid & 31;
    const int wid  = tid >> 5;
    const int wm   = (wid & 3) * 32;
    const int wn   = (wid >> 2) * 32;
    const int bm0  = blockIdx.y * 128, bn0 = blockIdx.x * 64;

    float acc[2][4][4];
    #pragma unroll
    for (int mi = 0; mi < 2; ++mi)
        #pragma unroll
        for (int ni = 0; ni < 4; ++ni)
            #pragma unroll
            for (int q = 0; q < 4; ++q) acc[mi][ni][q] = 0.0f;

    g2_issue(coh, qk, smem_base, smem_base + 2*ASZ*4, bm0, bn0, 0, tid);

    #pragma unroll 1
    for (int ch = 0; ch < 16; ++ch) {
        CP_WAIT0();
        __syncthreads();
        const int p = ch & 1;
        if (ch + 1 < 16) {
            const int q2 = p ^ 1;
            g2_issue(coh, qk, smem_base + q2*ASZ*4,
                     smem_base + (2*ASZ + q2*BSZ)*4, bm0, bn0, (ch+1)*16, tid);
        }
        const float* A2 = smf + p*ASZ;
        const float* B2 = smB + p*BSZ;
        #pragma unroll
        for (int ksl = 0; ksl < 2; ++ksl) {
            const int bc = ksl*8 + (lane & 3);
            float afr[2][4];
            #pragma unroll
            for (int mi = 0; mi < 2; ++mi) {
                int r = wm + (lane >> 2) + mi*16;
                afr[mi][0] = A2[r*AST + bc];
                afr[mi][1] = A2[(r+8)*AST + bc];
                afr[mi][2] = A2[r*AST + bc + 4];
                afr[mi][3] = A2[(r+8)*AST + bc + 4];
            }
            float bfr[4][2];
            #pragma unroll
            for (int ni = 0; ni < 4; ++ni) {
                int n = wn + ni*8 + (lane >> 2);
                bfr[ni][0] = B2[n*AST + bc];
                bfr[ni][1] = B2[n*AST + bc + 4];
            }
            #pragma unroll
            for (int mi = 0; mi < 2; ++mi)
                #pragma unroll
                for (int ni = 0; ni < 4; ++ni)
                    MMA_TF32(acc[mi][ni], afr[mi], bfr[ni]);
        }
    }

    // epilogue: factored scale, fast-math drive, spike + borderline flag
    const int r0 = bm0 + wm + (lane >> 2);
    const int c0 = bn0 + wn + (lane & 3)*2;
    const float gabs = fabsf(gainp[0]);
    const float scaleB = fmaxf(__fdiv_rn(__uint_as_float(g_absmax[1]), 7.0f), 1e-8f);

    #pragma unroll
    for (int mi = 0; mi < 2; ++mi)
        #pragma unroll
        for (int ni = 0; ni < 4; ++ni) {
            int col = c0 + ni*8;
            float b0 = __ldg(bias + col), b1 = __ldg(bias + col + 1);
            #pragma unroll
            for (int h = 0; h < 2; ++h) {
                int row = r0 + mi*16 + h*8;
                float lat = __ldg(latent + (row % T_));
                float2 dv, sv;
                #pragma unroll
                for (int q = 0; q < 2; ++q) {
                    float pre = fmaf(acc[mi][ni][h*2+q], scaleB, q ? b1 : b0);
                    float e   = __expf(-fabsf(pre));
                    float sp  = fmaxf(pre, 0.0f) + __logf(1.0f + e);
                    float d   = (sp * lat) * gabs;
                    unsigned idx = (unsigned)row * (unsigned)WID_ + (unsigned)(col + q);
                    unsigned bits = rbits32(idx);
                    float u = __uint_as_float((bits >> 9) | 0x3f800000u) - 1.0f;
                    float spike;
                    if (d >= 10.0f) spike = 1.0f;
                    else {
                        float t = __expf(-d);
                        spike = (u > t) ? 1.0f : 0.0f;
                        if (fabsf(u - t) < MARGIN * t) {
                            unsigned w = atomicAdd(&g_count, 1u);
                            if (w < WCAP) g_worklist[w] = idx;
                        }
                    }
                    if (q) { dv.y = d; sv.y = spike; } else { dv.x = d; sv.x = spike; }
                }
                size_t ob = (size_t)row * WID_ + col;
                *reinterpret_cast<float2*>(drv + ob) = dv;
                *reinterpret_cast<float2*>(spk + ob) = sv;
            }
        }
}

// ---------------- exact fp32 fixup for borderline spikes (reference semantics) --------
__global__ void fixup_k(const float* __restrict__ co, const float* __restrict__ qfc1,
                        const float* __restrict__ bias, const float* __restrict__ latent,
                        const float* __restrict__ gainp, float* __restrict__ spk)
{
    __shared__ float red[4];
    const unsigned n = (g_count < WCAP) ? g_count : WCAP;
    const float gabs = fabsf(gainp[0]);
    const int tid = threadIdx.x;   // 128
    for (unsigned i = blockIdx.x; i < n; i += gridDim.x) {
        unsigned idx = g_worklist[i];
        int row = idx >> 12, col = idx & (WID_-1);
        const float* cr = co + (size_t)row * RED_;
        const float* wr = qfc1 + (size_t)col * RED_;
        float s = cr[tid]*wr[tid] + cr[tid+128]*wr[tid+128];
        #pragma unroll
        for (int o = 16; o; o >>= 1) s += __shfl_xor_sync(0xffffffffu, s, o);
        if ((tid & 31) == 0) red[tid >> 5] = s;
        __syncthreads();
        if (tid == 0) {
            float pre = (red[0]+red[1]) + (red[2]+red[3]) + bias[col];
            float spl = fmaxf(pre, 0.0f) + log1pf(expf(-fabsf(pre)));
            float d   = (spl * latent[row % T_]) * gabs;
            unsigned bits = rbits32(idx);
            float u = __uint_as_float((bits >> 9) | 0x3f800000u) - 1.0f;
            spk[idx] = (d >= 10.0f) ? 1.0f : ((logf(u) > -d) ? 1.0f : 0.0f);
        }
        __syncthreads();
    }
}

// ---------------- decay-weighted temporal reduction ----------------
__global__ void weighted_k(const float* __restrict__ spikes) {
    __shared__ float decay[T_];
    int tid = threadIdx.x;
    if (tid < T_) decay[tid] = expf(-2.0f + (float)tid * (2.0f/99.0f));
    __syncthreads();
    int idx = blockIdx.x * blockDim.x + tid;
    if (idx >= B_*WID_) return;
    int b = idx >> 12, w = idx & (WID_-1);
    const float* sp = spikes + (size_t)b*T_*WID_ + w;
    float s = 0.0f;
    #pragma unroll 4
    for (int t = 0; t < T_; ++t) s += sp[(size_t)t*WID_] * decay[t];
    g_wsum[idx] = s;
}

// ---------------- logits ----------------
__global__ void logits_k(const float* __restrict__ bias, float* __restrict__ out) {
    int bc = blockIdx.x;
    int b = bc / CLS_, c = bc % CLS_;
    const float* wr = g_wsum + (size_t)b*WID_;
    const float* fr = g_qfc2 + (size_t)c*WID_;
    float s = 0.0f;
    for (int i = threadIdx.x; i < WID_; i += 128) s += wr[i]*fr[i];
    #pragma unroll
    for (int o = 16; o; o >>= 1) s += __shfl_xor_sync(0xffffffffu, s, o);
    __shared__ float red[4];
    if ((threadIdx.x & 31) == 0) red[threadIdx.x >> 5] = s;
    __syncthreads();
    if (threadIdx.x == 0) out[bc] = (red[0]+red[1]+red[2]+red[3]) + bias[c];
}

// ---------------- launcher ----------------
extern "C" void kernel_launch(void* const* d_in, const int* in_sizes, int n_in,
                              void* d_out, int out_size) {
    (void)in_sizes; (void)n_in; (void)out_size;
    const float* x        = (const float*)d_in[0];
    const float* latent   = (const float*)d_in[1];
    const float* spatialW = (const float*)d_in[2];
    const float* spatialB = (const float*)d_in[3];
    const float* convW    = (const float*)d_in[4];
    const float* convB    = (const float*)d_in[5];
    const float* fc1W     = (const float*)d_in[6];
    const float* fc1B     = (const float*)d_in[7];
    const float* fc2W     = (const float*)d_in[8];
    const float* fc2B     = (const float*)d_in[9];
    const float* gain     = (const float*)d_in[10];

    float* out        = (float*)d_out;
    float* out_logits = out;
    float* out_spk    = out + (CLS_*B_);
    float* out_drv    = out + (CLS_*B_) + (size_t)NELEM_;

    float *qsp, *qfc1, *qk, *qfc2, *cwt, *xp, *co, *coh;
    cudaGetSymbolAddress((void**)&qsp,  g_qsp);
    cudaGetSymbolAddress((void**)&qfc1, g_qfc1);
    cudaGetSymbolAddress((void**)&qk,   g_qk);
    cudaGetSymbolAddress((void**)&qfc2, g_qfc2);
    cudaGetSymbolAddress((void**)&cwt,  g_convWt);
    cudaGetSymbolAddress((void**)&xp,   g_xp);
    cudaGetSymbolAddress((void**)&co,   g_co);
    cudaGetSymbolAddress((void**)&coh,  g_coh);

    static bool attr_set = false;
    if (!attr_set) {
        cudaFuncSetAttribute(g2tf_k, cudaFuncAttributeMaxDynamicSharedMemorySize, G2_SMEM);
        attr_set = true;
    }

    init_k<<<1, 32>>>();
    absmax3_k<<<384, 256>>>(spatialW, fc1W, fc2W);
    prep_k<<<NPREP_/256, 256>>>(spatialW, fc1W, fc2W, convW);

    // GEMM1: xp = relu(x @ qsp^T + b)   (exact fp32 FFMA2)
    sgemm_k<0,0><<<dim3(RED_/128, ROWS_/128), 256>>>(x, qsp, spatialB, xp, nullptr, INF_, RED_);
    // conv (fused im2col): co = relu(im2col(xp) @ cwt^T + cb), also emits coh = tf32(co)
    sgemm_k<1,1><<<dim3(RED_/128, ROWS_/128), 256>>>(xp, cwt, convB, co, coh, KC_, RED_);
    // GEMM2 (tf32 1-pass, int4-level B, scale factored) + drive/spike + flags
    g2tf_k<<<dim3(WID_/64, ROWS_/128), 256, G2_SMEM>>>(coh, qk, fc1B,
                                                       latent, gain, out_drv, out_spk);
    // exact recompute of borderline spikes
    fixup_k<<<2048, 128>>>(co, qfc1, fc1B, latent, gain, out_spk);
    weighted_k<<<(B_*WID_ + 255)/256, 256>>>(out_spk);
    logits_k<<<B_*CLS_, 128>>>(fc2B, out_logits);
}